// round 13
// baseline (speedup 1.0000x reference)
#include <cuda_runtime.h>
#include <cuda_bf16.h>
#include <math.h>
#include <stdint.h>

// Problem constants
#define BATCH 4
#define TLEN  1024
#define EDIM  1024
#define HEADS 16
#define SDIM  64
#define P2    2047   // 2*t - 1

// ---------------------------------------------------------------------------
// Scratch (device globals — no runtime allocation allowed)
// ---------------------------------------------------------------------------
__device__ float g_V  [(size_t)BATCH * TLEN * EDIM];
__device__ float g_dpt[(size_t)BATCH * HEADS * TLEN];
__device__ float g_cpp[(size_t)HEADS * P2];
// bf16 hi/lo planes
__device__ __nv_bfloat16 g_Xh [(size_t)BATCH * TLEN * EDIM];
__device__ __nv_bfloat16 g_Xl [(size_t)BATCH * TLEN * EDIM];
__device__ __nv_bfloat16 g_Psrch[(size_t)P2 * EDIM];
__device__ __nv_bfloat16 g_Psrcl[(size_t)P2 * EDIM];
__device__ __nv_bfloat16 g_Wh [(size_t)5 * EDIM * EDIM];  // transposed [N,K]
__device__ __nv_bfloat16 g_Wl [(size_t)5 * EDIM * EDIM];
__device__ __nv_bfloat16 g_Qh [(size_t)BATCH * TLEN * EDIM];
__device__ __nv_bfloat16 g_Ql [(size_t)BATCH * TLEN * EDIM];
__device__ __nv_bfloat16 g_Kh [(size_t)BATCH * TLEN * EDIM];
__device__ __nv_bfloat16 g_Kl [(size_t)BATCH * TLEN * EDIM];
__device__ __nv_bfloat16 g_KPh[(size_t)P2 * EDIM];
__device__ __nv_bfloat16 g_KPl[(size_t)P2 * EDIM];
__device__ __nv_bfloat16 g_ATTh[(size_t)BATCH * TLEN * EDIM];
__device__ __nv_bfloat16 g_ATTl[(size_t)BATCH * TLEN * EDIM];

// ---------------------------------------------------------------------------
// helpers
// ---------------------------------------------------------------------------
__device__ __forceinline__ void msplit(float x, uint32_t& hi, uint32_t& lo) {
    uint32_t h = __float_as_uint(x) & 0xFFFFE000u;   // tf32 mask split
    hi = h;
    lo = __float_as_uint(x - __uint_as_float(h));
}
__device__ __forceinline__ void mma_tf32(float* c,
    uint32_t a0, uint32_t a1, uint32_t a2, uint32_t a3,
    uint32_t b0, uint32_t b1)
{
    asm volatile(
        "mma.sync.aligned.m16n8k8.row.col.f32.tf32.tf32.f32 "
        "{%0,%1,%2,%3}, {%4,%5,%6,%7}, {%8,%9}, {%0,%1,%2,%3};"
        : "+f"(c[0]), "+f"(c[1]), "+f"(c[2]), "+f"(c[3])
        : "r"(a0), "r"(a1), "r"(a2), "r"(a3), "r"(b0), "r"(b1));
}
__device__ __forceinline__ void mma_x3(float* c,
    const uint32_t* ah, const uint32_t* al,
    uint32_t bh0, uint32_t bh1, uint32_t bl0, uint32_t bl1)
{
    mma_tf32(c, al[0], al[1], al[2], al[3], bh0, bh1);
    mma_tf32(c, ah[0], ah[1], ah[2], ah[3], bl0, bl1);
    mma_tf32(c, ah[0], ah[1], ah[2], ah[3], bh0, bh1);
}
__device__ __forceinline__ void mma_bf16(float* c,
    uint32_t a0, uint32_t a1, uint32_t a2, uint32_t a3,
    uint32_t b0, uint32_t b1)
{
    asm volatile(
        "mma.sync.aligned.m16n8k16.row.col.f32.bf16.bf16.f32 "
        "{%0,%1,%2,%3}, {%4,%5,%6,%7}, {%8,%9}, {%0,%1,%2,%3};"
        : "+f"(c[0]), "+f"(c[1]), "+f"(c[2]), "+f"(c[3])
        : "r"(a0), "r"(a1), "r"(a2), "r"(a3), "r"(b0), "r"(b1));
}
__device__ __forceinline__ void mma_bf16_x3(float* c,
    const uint32_t* ah, const uint32_t* al,
    uint32_t bh0, uint32_t bh1, uint32_t bl0, uint32_t bl1)
{
    mma_bf16(c, al[0], al[1], al[2], al[3], bh0, bh1);
    mma_bf16(c, ah[0], ah[1], ah[2], ah[3], bl0, bl1);
    mma_bf16(c, ah[0], ah[1], ah[2], ah[3], bh0, bh1);
}
// ldmatrix x4: loads a 16x16 b16 tile (A frag) or two 8-col B tiles.
// Canonical lane->addr: row = base_row + (lane&15), k-half = lane>>4.
__device__ __forceinline__ void ldm_x4(uint32_t* r, uint32_t saddr) {
    asm volatile(
        "ldmatrix.sync.aligned.m8n8.x4.shared.b16 {%0,%1,%2,%3}, [%4];"
        : "=r"(r[0]), "=r"(r[1]), "=r"(r[2]), "=r"(r[3]) : "r"(saddr));
}
// pack two fp32 into (hi bf16x2, lo bf16x2)
__device__ __forceinline__ void bsplit2(float v0, float v1,
                                        uint32_t& hi, uint32_t& lo)
{
    __nv_bfloat162 h = __float22bfloat162_rn(make_float2(v0, v1));
    float r0 = v0 - __bfloat162float(h.x);
    float r1 = v1 - __bfloat162float(h.y);
    __nv_bfloat162 l = __float22bfloat162_rn(make_float2(r0, r1));
    hi = *(uint32_t*)&h;
    lo = *(uint32_t*)&l;
}
// reconstruct 2 fp32 from hi/lo words
__device__ __forceinline__ float2 brecon2(uint32_t h, uint32_t l) {
    __nv_bfloat162 hb = *(__nv_bfloat162*)&h;
    __nv_bfloat162 lb = *(__nv_bfloat162*)&l;
    return make_float2(__bfloat162float(hb.x) + __bfloat162float(lb.x),
                       __bfloat162float(hb.y) + __bfloat162float(lb.y));
}

// cp.async helpers (baseline PTX, sm_80+); v=false -> zero-fill 16B
__device__ __forceinline__ void cpa16(void* smem_dst, const void* gsrc, bool v) {
    uint32_t s = (uint32_t)__cvta_generic_to_shared(smem_dst);
    int sz = v ? 16 : 0;
    asm volatile("cp.async.cg.shared.global [%0], [%1], 16, %2;"
                 :: "r"(s), "l"(gsrc), "r"(sz) : "memory");
}
#define CP_COMMIT() asm volatile("cp.async.commit_group;" ::: "memory")
#define CP_WAIT1()  asm volatile("cp.async.wait_group 1;" ::: "memory")
#define CP_WAIT0()  asm volatile("cp.async.wait_group 0;" ::: "memory")

// ---------------------------------------------------------------------------
// Transpose 5 weights into bf16 hi/lo planes
// ---------------------------------------------------------------------------
__global__ void __launch_bounds__(256) transpose5_kernel(
    const float* __restrict__ W0, const float* __restrict__ W1,
    const float* __restrict__ W2, const float* __restrict__ W3,
    const float* __restrict__ W4,
    __nv_bfloat16* __restrict__ dstHi, __nv_bfloat16* __restrict__ dstLo)
{
    __shared__ float t[32][33];
    int z = blockIdx.z;
    const float* src = (z == 0) ? W0 : (z == 1) ? W1 : (z == 2) ? W2
                     : (z == 3) ? W3 : W4;
    size_t base = (size_t)z * EDIM * EDIM;
    int bx = blockIdx.x * 32, by = blockIdx.y * 32;
    int x = threadIdx.x, y = threadIdx.y;   // block (32, 8)
    #pragma unroll
    for (int i = 0; i < 32; i += 8)
        t[y + i][x] = src[(size_t)(by + y + i) * EDIM + bx + x];
    __syncthreads();
    #pragma unroll
    for (int i = 0; i < 32; i += 8) {
        float v = t[x][y + i];
        __nv_bfloat16 hb = __float2bfloat16_rn(v);
        size_t o = base + (size_t)(bx + y + i) * EDIM + by + x;
        dstHi[o] = hb;
        dstLo[o] = __float2bfloat16_rn(v - __bfloat162float(hb));
    }
}

// ---------------------------------------------------------------------------
// Convert fp32 array to bf16 hi/lo planes (pairwise)
// ---------------------------------------------------------------------------
__global__ void __launch_bounds__(256) cvt_planes_kernel(
    const float2* __restrict__ src, uint32_t* __restrict__ hi,
    uint32_t* __restrict__ lo, int npairs)
{
    int i = blockIdx.x * 256 + threadIdx.x;
    if (i >= npairs) return;
    float2 v = src[i];
    uint32_t h, l;
    bsplit2(v.x, v.y, h, l);
    hi[i] = h;
    lo[i] = l;
}

// ---------------------------------------------------------------------------
// bf16x3 tensor-core GEMM tile with ldmatrix fragment loads.
// ---------------------------------------------------------------------------
#define GPW 20                         // uint32 words per smem plane row
#define PLANE_W (128 * GPW)            // 2560 words per plane
#define GEMM_SMEM_BYTES (8 * PLANE_W * 4)   // 81920 B

__device__ __forceinline__ void gemm_stage_bf16(
    uint32_t* s,
    const uint32_t* __restrict__ Ah, const uint32_t* __restrict__ Al,
    const uint32_t* __restrict__ Bh, const uint32_t* __restrict__ Bl,
    int M, int bm, int bn, int koffw, int tid)
{
    #pragma unroll
    for (int r = 0; r < 2; r++) {
        int slot = tid + 256 * r;          // 0..511
        int row = slot >> 2, ch = (slot & 3) * 4;
        int grow = bm + row;
        bool v = grow < M;
        size_t ga = (size_t)(v ? grow : 0) * 512 + koffw + ch;
        size_t gb = (size_t)(bn + row) * 512 + koffw + ch;
        uint32_t* sd = s + row * GPW + ch;
        cpa16(sd,               &Ah[ga], v);
        cpa16(sd + PLANE_W,     &Al[ga], v);
        cpa16(sd + 2 * PLANE_W, &Bh[gb], true);
        cpa16(sd + 3 * PLANE_W, &Bl[gb], true);
    }
    CP_COMMIT();
}

__device__ __forceinline__ void gemm_tile(
    const uint32_t* __restrict__ Ah, const uint32_t* __restrict__ Al,
    const uint32_t* __restrict__ Bh, const uint32_t* __restrict__ Bl,
    const float* __restrict__ bias, float* __restrict__ Cf,
    uint32_t* __restrict__ Ch, uint32_t* __restrict__ Cl,
    int M, int hasBias, int bm, int bn)
{
    extern __shared__ uint32_t gsm[];
    uint32_t* buf0 = gsm;
    uint32_t* buf1 = gsm + 4 * PLANE_W;

    const int tid  = threadIdx.x;
    const int wid  = tid >> 5;
    const int lane = tid & 31;
    const int wm = wid & 1;
    const int wn = wid >> 1;
    const int g = lane >> 2;
    const int t = lane & 3;
    // ldmatrix per-lane byte offset within a tile: row lane&15, k-half lane>>4
    const uint32_t lz = (((lane & 15) * GPW) + ((lane >> 4) << 2)) * 4;
    const uint32_t smem0 = (uint32_t)__cvta_generic_to_shared(gsm);

    gemm_stage_bf16(buf0, Ah, Al, Bh, Bl, M, bm, bn, 0,  tid);
    gemm_stage_bf16(buf1, Ah, Al, Bh, Bl, M, bm, bn, 16, tid);

    float acc[4][4][4];
    #pragma unroll
    for (int mi = 0; mi < 4; mi++)
        #pragma unroll
        for (int ni = 0; ni < 4; ni++)
            #pragma unroll
            for (int q = 0; q < 4; q++) acc[mi][ni][q] = 0.f;

    #pragma unroll 1
    for (int kt = 0; kt < 32; kt++) {
        if (kt + 1 < 32) CP_WAIT1(); else CP_WAIT0();
        __syncthreads();
        const uint32_t bufo = (kt & 1) ? (4 * PLANE_W * 4) : 0;
        const uint32_t aho = smem0 + bufo + lz;
        const uint32_t alo = aho + PLANE_W * 4;
        const uint32_t bho = alo + PLANE_W * 4;
        const uint32_t blo = bho + PLANE_W * 4;

        #pragma unroll
        for (int ks = 0; ks < 2; ks++) {
            const uint32_t kbB = (uint32_t)(ks * 8) * 4;
            uint32_t ah[4][4], al[4][4], bh[2][4], bl[2][4];
            #pragma unroll
            for (int mi = 0; mi < 4; mi++) {
                uint32_t ro = (uint32_t)((wm * 64 + mi * 16) * GPW) * 4 + kbB;
                ldm_x4(ah[mi], aho + ro);
                ldm_x4(al[mi], alo + ro);
            }
            #pragma unroll
            for (int p = 0; p < 2; p++) {
                uint32_t ro = (uint32_t)((wn * 32 + p * 16) * GPW) * 4 + kbB;
                ldm_x4(bh[p], bho + ro);
                ldm_x4(bl[p], blo + ro);
            }
            #pragma unroll
            for (int ni = 0; ni < 4; ni++) {
                int p = ni >> 1, o = ni & 1;
                uint32_t bh0 = bh[p][o], bh1 = bh[p][o + 2];
                uint32_t bl0 = bl[p][o], bl1 = bl[p][o + 2];
                #pragma unroll
                for (int mi = 0; mi < 4; mi++)
                    mma_bf16_x3(acc[mi][ni], ah[mi], al[mi], bh0, bh1, bl0, bl1);
            }
        }
        __syncthreads();
        if (kt + 2 < 32)
            gemm_stage_bf16((kt & 1) ? buf1 : buf0, Ah, Al, Bh, Bl,
                            M, bm, bn, (kt + 2) * 16, tid);
    }

    #pragma unroll
    for (int mi = 0; mi < 4; mi++) {
        int row0 = bm + wm * 64 + mi * 16 + g;
        #pragma unroll
        for (int ni = 0; ni < 4; ni++) {
            int col = bn + wn * 32 + ni * 8 + t * 2;
            if (Cf) {
                float b0 = hasBias ? bias[col] : 0.f;
                float b1 = hasBias ? bias[col + 1] : 0.f;
                if (row0 < M) {
                    Cf[(size_t)row0 * EDIM + col]     = acc[mi][ni][0] + b0;
                    Cf[(size_t)row0 * EDIM + col + 1] = acc[mi][ni][1] + b1;
                }
                if (row0 + 8 < M) {
                    Cf[(size_t)(row0 + 8) * EDIM + col]     = acc[mi][ni][2] + b0;
                    Cf[(size_t)(row0 + 8) * EDIM + col + 1] = acc[mi][ni][3] + b1;
                }
            } else {
                uint32_t h, l;
                if (row0 < M) {
                    bsplit2(acc[mi][ni][0], acc[mi][ni][1], h, l);
                    size_t w = (size_t)row0 * 512 + (col >> 1);
                    Ch[w] = h; Cl[w] = l;
                }
                if (row0 + 8 < M) {
                    bsplit2(acc[mi][ni][2], acc[mi][ni][3], h, l);
                    size_t w = (size_t)(row0 + 8) * 512 + (col >> 1);
                    Ch[w] = h; Cl[w] = l;
                }
            }
        }
    }
}

// Fused projections: z=0 Q planes, z=1 K planes, z=2 V fp32, z=3 KP planes.
__global__ void __launch_bounds__(256, 2) fused_gemm_kernel(
    const uint32_t* __restrict__ Xh, const uint32_t* __restrict__ Xl,
    const uint32_t* __restrict__ Ph, const uint32_t* __restrict__ Pl,
    const uint32_t* __restrict__ Wh, const uint32_t* __restrict__ Wl,
    uint32_t* __restrict__ Qh, uint32_t* __restrict__ Ql,
    uint32_t* __restrict__ Kh, uint32_t* __restrict__ Kl,
    float* __restrict__ Vb,
    uint32_t* __restrict__ KPh, uint32_t* __restrict__ KPl)
{
    const int z = blockIdx.z;
    const uint32_t* Ah = (z < 3) ? Xh : Ph;
    const uint32_t* Al = (z < 3) ? Xl : Pl;
    const int M = (z < 3) ? (BATCH * TLEN) : P2;
    const int bm = blockIdx.y * 128;
    if (bm >= M) return;
    const uint32_t* Bh = Wh + (size_t)z * EDIM * EDIM / 2;
    const uint32_t* Bl = Wl + (size_t)z * EDIM * EDIM / 2;
    float* Cf = (z == 2) ? Vb : nullptr;
    uint32_t* Ch = (z == 0) ? Qh : (z == 1) ? Kh : (z == 3) ? KPh : nullptr;
    uint32_t* Cl = (z == 0) ? Ql : (z == 1) ? Kl : (z == 3) ? KPl : nullptr;
    gemm_tile(Ah, Al, Bh, Bl, nullptr, Cf, Ch, Cl, M, 0, bm, blockIdx.x * 128);
}

__global__ void __launch_bounds__(256, 2) gemmU_kernel(
    const uint32_t* __restrict__ Ah, const uint32_t* __restrict__ Al,
    const uint32_t* __restrict__ Bh, const uint32_t* __restrict__ Bl,
    const float* __restrict__ bias, float* __restrict__ C)
{
    gemm_tile(Ah, Al, Bh, Bl, bias, C, nullptr, nullptr, BATCH * TLEN, 1,
              blockIdx.y * 128, blockIdx.x * 128);
}

// ---------------------------------------------------------------------------
// Fused dpt + cpp (reads bf16 planes, reconstructs hi+lo)
// ---------------------------------------------------------------------------
__global__ void __launch_bounds__(256) dptcpp_kernel(
    const uint32_t* __restrict__ Kh, const uint32_t* __restrict__ Kl,
    const uint32_t* __restrict__ KPh, const uint32_t* __restrict__ KPl,
    const float* __restrict__ parma, const float* __restrict__ parmb,
    float* __restrict__ dpt, float* __restrict__ cpp)
{
    int idx = blockIdx.x * 256 + threadIdx.x;
    if (idx < BATCH * HEADS * TLEN) {
        int j = idx & (TLEN - 1);
        int h = (idx >> 10) & (HEADS - 1);
        int b = idx >> 14;
        size_t base = (size_t)(b * TLEN + j) * 512 + h * 32;
        const float* pa = parma + h * SDIM;
        float s = 0.f;
        #pragma unroll
        for (int w = 0; w < 32; w++) {
            float2 f = brecon2(Kh[base + w], Kl[base + w]);
            s = fmaf(pa[2 * w], f.x, s);
            s = fmaf(pa[2 * w + 1], f.y, s);
        }
        dpt[idx] = s;
    } else {
        int i2 = idx - BATCH * HEADS * TLEN;
        if (i2 >= HEADS * P2) return;
        int h = i2 / P2;
        int p = i2 - h * P2;
        size_t base = (size_t)p * 512 + h * 32;
        const float* pb = parmb + h * SDIM;
        float s = 0.f;
        #pragma unroll
        for (int w = 0; w < 32; w++) {
            float2 f = brecon2(KPh[base + w], KPl[base + w]);
            s = fmaf(pb[2 * w], f.x, s);
            s = fmaf(pb[2 * w + 1], f.y, s);
        }
        cpp[i2] = s;
    }
}

// ---------------------------------------------------------------------------
// Tensor-core attention: scores = bf16x3 (k16, ldmatrix) on Q/K/KP planes;
// softmax fp32; PV = tf32x3. Band-masked E fragments.
// ---------------------------------------------------------------------------
#define QW 36    // word stride for bf16 plane rows
#define VP 72    // V fp32 stride
#define SP 196   // S matrix stride (floats)

#define OFF_QH 0
#define OFF_QL 2304
#define OFF_BH 4608
#define OFF_BL 11520
#define OFF_VS 18432
#define OFF_PS 23040
#define OFF_DP 27392
#define OFF_CP 27456
#define OFF_SC 27584
#define OFF_LS 27648
#define ATTN_SMEM_BYTES (27712 * 4)

__global__ void __launch_bounds__(256, 2) attn_kernel(
    const uint32_t* __restrict__ Qh, const uint32_t* __restrict__ Ql,
    const uint32_t* __restrict__ Kh, const uint32_t* __restrict__ Kl,
    const float* __restrict__ V,
    const uint32_t* __restrict__ KPh, const uint32_t* __restrict__ KPl,
    const float* __restrict__ dpt, const float* __restrict__ cpp,
    uint32_t* __restrict__ Oh, uint32_t* __restrict__ Ol)
{
    extern __shared__ uint32_t smw[];
    uint32_t* Qhs = smw + OFF_QH;       // [64][QW]
    uint32_t* Qls = smw + OFF_QL;
    uint32_t* Bhs = smw + OFF_BH;       // [192][QW] K rows 0..63, KP 64..191
    uint32_t* Bls = smw + OFF_BL;
    float* Ssm  = (float*)(smw + OFF_BH);   // [64][SP] aliases Bh/Bl block
    float* Vs   = (float*)(smw + OFF_VS);   // [64][VP]
    float* Psm  = (float*)(smw + OFF_PS);   // [64][68]
    float* dpts = (float*)(smw + OFF_DP);
    float* cpps = (float*)(smw + OFF_CP);
    float* scale_sm = (float*)(smw + OFF_SC);
    float* lsum_sm  = (float*)(smw + OFF_LS);

    const int tid  = threadIdx.x;
    const int lane = tid & 31;
    const int wid  = tid >> 5;
    const int g = lane >> 2;
    const int t = lane & 3;
    const int rm = (wid & 1) * 32;      // scores m-base
    const int cn = (wid >> 1) * 48;     // scores n-base
    const int sm0 = (wid & 3) * 16;     // PV m-slice
    const int pn0 = (wid >> 2) * 32;    // PV n-slice
    const int tx = tid & 15, ty = tid >> 4;
    const uint32_t lzq = (((lane & 15) * QW) + ((lane >> 4) << 2)) * 4;
    const uint32_t smb = (uint32_t)__cvta_generic_to_shared(smw);

    const int b = blockIdx.z, h = blockIdx.y;
    const int it = (int)gridDim.x - 1 - (int)blockIdx.x;
    const int I0 = it * 64;
    const int hw = h * 32;

    // Stage Q planes once
    for (int idx = tid; idx < 512; idx += 256) {
        int r = idx >> 3, w = (idx & 7) * 4;
        size_t gq = (size_t)(b * TLEN + I0 + r) * 512 + hw + w;
        cpa16(&Qhs[r * QW + w], &Qh[gq], true);
        cpa16(&Qls[r * QW + w], &Ql[gq], true);
    }
    CP_COMMIT();

    float m_r[4], l_r[4];
    #pragma unroll
    for (int i = 0; i < 4; i++) { m_r[i] = -INFINITY; l_r[i] = 0.f; }
    float o_acc[4][4];
    #pragma unroll
    for (int n = 0; n < 4; n++)
        #pragma unroll
        for (int q = 0; q < 4; q++) o_acc[n][q] = 0.f;

    for (int jt = 0; jt <= it; jt++) {
        const int J0 = jt * 64;
        const int pbase = I0 + J0;
        const int d = I0 - J0;

        __syncthreads();

        for (int idx = tid; idx < 512; idx += 256) {
            int c = idx >> 3, w = (idx & 7) * 4;
            size_t gk = (size_t)(b * TLEN + J0 + c) * 512 + hw + w;
            cpa16(&Bhs[c * QW + w], &Kh[gk], true);
            cpa16(&Bls[c * QW + w], &Kl[gk], true);
        }
        for (int idx = tid; idx < 1024; idx += 256) {
            int pl = idx >> 3, w = (idx & 7) * 4;
            int p = pbase + pl;
            bool v = p < P2;
            size_t gp = (size_t)(v ? p : 0) * 512 + hw + w;
            cpa16(&Bhs[(64 + pl) * QW + w], &KPh[gp], v);
            cpa16(&Bls[(64 + pl) * QW + w], &KPl[gp], v);
        }
        for (int idx = tid; idx < 1024; idx += 256) {
            int j = idx >> 4, s4 = (idx & 15) << 2;
            cpa16(&Vs[j * VP + s4],
                  &V[((size_t)(b * TLEN + J0 + j)) * EDIM + h * SDIM + s4], true);
        }
        CP_COMMIT();
        if (tid < 64) dpts[tid] = dpt[((size_t)(b * HEADS + h)) * TLEN + J0 + tid];
        if (tid < 128) {
            int p = pbase + tid;
            cpps[tid] = (p < P2) ? cpp[(size_t)h * P2 + p] : 0.f;
        }
        CP_WAIT0();
        __syncthreads();

        // Fragment need-masks (warp-uniform)
        bool need[2][6];
        #pragma unroll
        for (int mi = 0; mi < 2; mi++) {
            int m0 = rm + 16 * mi;
            int cmax = m0 + 15 + d; if (cmax > 63) cmax = 63;
            #pragma unroll
            for (int nt = 0; nt < 6; nt++) {
                int n0 = cn + nt * 8;
                if (n0 < 64) {
                    need[mi][nt] = (n0 <= m0 + 15 + d);
                } else {
                    int pl0 = n0 - 64;
                    need[mi][nt] = (pl0 + 7 >= m0) && (pl0 <= m0 + 15 + cmax);
                }
            }
        }

        // ---- Scores mma: bf16x3 m16n8k16 via ldmatrix ----
        float sacc[2][6][4];
        #pragma unroll
        for (int mi = 0; mi < 2; mi++)
            #pragma unroll
            for (int n = 0; n < 6; n++)
                #pragma unroll
                for (int q = 0; q < 4; q++) sacc[mi][n][q] = 0.f;

        const uint32_t qh0 = smb + OFF_QH * 4 + lzq;
        const uint32_t ql0 = smb + OFF_QL * 4 + lzq;
        const uint32_t bh0b = smb + OFF_BH * 4 + lzq;
        const uint32_t bl0b = smb + OFF_BL * 4 + lzq;

        #pragma unroll
        for (int kc = 0; kc < 4; kc++) {
            const uint32_t kbB = (uint32_t)(kc * 8) * 4;
            uint32_t ah[2][4], al[2][4], bh[3][4], bl[3][4];
            #pragma unroll
            for (int mi = 0; mi < 2; mi++) {
                uint32_t ro = (uint32_t)((rm + 16 * mi) * QW) * 4 + kbB;
                ldm_x4(ah[mi], qh0 + ro);
                ldm_x4(al[mi], ql0 + ro);
            }
            #pragma unroll
            for (int p = 0; p < 3; p++) {
                uint32_t ro = (uint32_t)((cn + p * 16) * QW) * 4 + kbB;
                ldm_x4(bh[p], bh0b + ro);
                ldm_x4(bl[p], bl0b + ro);
            }
            #pragma unroll
            for (int nt = 0; nt < 6; nt++) {
                if (!need[0][nt] && !need[1][nt]) continue;
                int p = nt >> 1, o = nt & 1;
                uint32_t b0 = bh[p][o], b1 = bh[p][o + 2];
                uint32_t c0 = bl[p][o], c1 = bl[p][o + 2];
                if (need[0][nt])
                    mma_bf16_x3(sacc[0][nt], ah[0], al[0], b0, b1, c0, c1);
                if (need[1][nt])
                    mma_bf16_x3(sacc[1][nt], ah[1], al[1], b0, b1, c0, c1);
            }
        }

        __syncthreads();   // done reading B planes; overwrite as Ssm
        #pragma unroll
        for (int mi = 0; mi < 2; mi++) {
            int r0 = rm + 16 * mi + g;
            #pragma unroll
            for (int nt = 0; nt < 6; nt++) {
                if (!need[mi][nt]) continue;
                int n0 = cn + nt * 8 + 2 * t;
                Ssm[r0 * SP + n0]           = sacc[mi][nt][0];
                Ssm[r0 * SP + n0 + 1]       = sacc[mi][nt][1];
                Ssm[(r0 + 8) * SP + n0]     = sacc[mi][nt][2];
                Ssm[(r0 + 8) * SP + n0 + 1] = sacc[mi][nt][3];
            }
        }
        __syncthreads();

        // ---- Softmax (fp32 SIMT) ----
        #pragma unroll
        for (int i = 0; i < 4; i++) {
            int r = ty + 16 * i;
            float sc[4];
            float mx = -INFINITY;
            #pragma unroll
            for (int j = 0; j < 4; j++) {
                int c = tx + 16 * j;
                float v = Ssm[r * SP + c] + Ssm[r * SP + 64 + r + c]
                        + dpts[c] + cpps[r + c];
                if (c > r + d) v = -1e30f;
                sc[j] = v;
                mx = fmaxf(mx, v);
            }
            #pragma unroll
            for (int off = 8; off >= 1; off >>= 1)
                mx = fmaxf(mx, __shfl_xor_sync(0xffffffffu, mx, off));
            float mnew = fmaxf(m_r[i], mx);
            float scale = __expf(m_r[i] - mnew);
            m_r[i] = mnew;
            float rs = 0.f;
            #pragma unroll
            for (int j = 0; j < 4; j++) {
                float p = __expf(sc[j] - mnew);
                Psm[r * 68 + tx + 16 * j] = p;
                rs += p;
            }
            #pragma unroll
            for (int off = 8; off >= 1; off >>= 1)
                rs += __shfl_xor_sync(0xffffffffu, rs, off);
            l_r[i] = l_r[i] * scale + rs;
            if (tx == 0) {
                scale_sm[r] = scale;
                lsum_sm[r]  = l_r[i];
            }
        }
        __syncthreads();

        // ---- PV mma: O = O*scale + P @ V (tf32x3) ----
        const float sA = scale_sm[sm0 + g];
        const float sB = scale_sm[sm0 + g + 8];
        #pragma unroll
        for (int nt = 0; nt < 4; nt++) {
            o_acc[nt][0] *= sA; o_acc[nt][1] *= sA;
            o_acc[nt][2] *= sB; o_acc[nt][3] *= sB;
        }
        #pragma unroll
        for (int kk = 0; kk < 64; kk += 8) {
            uint32_t ah[4], al[4];
            msplit(Psm[(sm0 + g) * 68 + kk + t],         ah[0], al[0]);
            msplit(Psm[(sm0 + g + 8) * 68 + kk + t],     ah[1], al[1]);
            msplit(Psm[(sm0 + g) * 68 + kk + t + 4],     ah[2], al[2]);
            msplit(Psm[(sm0 + g + 8) * 68 + kk + t + 4], ah[3], al[3]);
            #pragma unroll
            for (int nt = 0; nt < 4; nt++) {
                int n0 = pn0 + nt * 8;
                uint32_t bh0, bl0, bh1, bl1;
                msplit(Vs[(kk + t) * VP + n0 + g],     bh0, bl0);
                msplit(Vs[(kk + t + 4) * VP + n0 + g], bh1, bl1);
                mma_x3(o_acc[nt], ah, al, bh0, bh1, bl0, bl1);
            }
        }
    }

    __syncthreads();
    const float invA = 1.f / lsum_sm[sm0 + g];
    const float invB = 1.f / lsum_sm[sm0 + g + 8];
    const size_t row0 = (size_t)(b * TLEN + I0 + sm0 + g) * EDIM;
    const size_t row1 = row0 + 8 * EDIM;
    #pragma unroll
    for (int nt = 0; nt < 4; nt++) {
        size_t col = (size_t)h * SDIM + pn0 + nt * 8 + 2 * t;   // even
        uint32_t hA, lA, hB, lB;
        bsplit2(o_acc[nt][0] * invA, o_acc[nt][1] * invA, hA, lA);
        bsplit2(o_acc[nt][2] * invB, o_acc[nt][3] * invB, hB, lB);
        Oh[(row0 + col) >> 1] = hA;
        Ol[(row0 + col) >> 1] = lA;
        Oh[(row1 + col) >> 1] = hB;
        Ol[(row1 + col) >> 1] = lB;
    }
}

// ---------------------------------------------------------------------------
// Launch
// ---------------------------------------------------------------------------
extern "C" void kernel_launch(void* const* d_in, const int* in_sizes, int n_in,
                              void* d_out, int out_size)
{
    const float* x     = (const float*)d_in[0];
    const float* Wq    = (const float*)d_in[1];
    const float* Wk    = (const float*)d_in[2];
    const float* Wkp   = (const float*)d_in[3];
    const float* Wv    = (const float*)d_in[4];
    const float* Wu    = (const float*)d_in[5];
    const float* bu    = (const float*)d_in[6];
    const float* parma = (const float*)d_in[7];
    const float* parmb = (const float*)d_in[8];
    const float* pos   = (const float*)d_in[9];
    float* out = (float*)d_out;

    float *Vb, *dptb, *cppb;
    void *Xh, *Xl, *Ph, *Pl, *Wh, *Wl, *Qh, *Ql, *Kh, *Kl, *KPh, *KPl, *ATTh, *ATTl;
    cudaGetSymbolAddress((void**)&Vb,   g_V);
    cudaGetSymbolAddress((void**)&dptb, g_dpt);
    cudaGetSymbolAddress((void**)&cppb, g_cpp);
    cudaGetSymbolAddress(&Xh,  g_Xh);
    cudaGetSymbolAddress(&Xl,  g_Xl);
    cudaGetSymbolAddress(&Ph,  g_Psrch);
    cudaGetSymbolAddress(&Pl,  g_Psrcl);
    cudaGetSymbolAddress(&Wh,  g_Wh);
    cudaGetSymbolAddress(&Wl,  g_Wl);
    cudaGetSymbolAddress(&Qh,  g_Qh);
    cudaGetSymbolAddress(&Ql,  g_Ql);
    cudaGetSymbolAddress(&Kh,  g_Kh);
    cudaGetSymbolAddress(&Kl,  g_Kl);
    cudaGetSymbolAddress(&KPh, g_KPh);
    cudaGetSymbolAddress(&KPl, g_KPl);
    cudaGetSymbolAddress(&ATTh, g_ATTh);
    cudaGetSymbolAddress(&ATTl, g_ATTl);

    // 1) transpose + split weights into bf16 planes
    transpose5_kernel<<<dim3(32, 32, 5), dim3(32, 8)>>>(
        Wq, Wk, Wv, Wkp, Wu, (__nv_bfloat16*)Wh, (__nv_bfloat16*)Wl);

    // 2) split x and pos into planes
    const int xpairs = BATCH * TLEN * EDIM / 2;
    const int ppairs = P2 * EDIM / 2;
    cvt_planes_kernel<<<(xpairs + 255) / 256, 256>>>(
        (const float2*)x, (uint32_t*)Xh, (uint32_t*)Xl, xpairs);
    cvt_planes_kernel<<<(ppairs + 255) / 256, 256>>>(
        (const float2*)pos, (uint32_t*)Ph, (uint32_t*)Pl, ppairs);

    // 3) fused projections: Q/K/KP -> bf16 planes, V -> fp32
    cudaFuncSetAttribute(fused_gemm_kernel,
                         cudaFuncAttributeMaxDynamicSharedMemorySize,
                         GEMM_SMEM_BYTES);
    fused_gemm_kernel<<<dim3(8, 32, 4), 256, GEMM_SMEM_BYTES>>>(
        (const uint32_t*)Xh, (const uint32_t*)Xl,
        (const uint32_t*)Ph, (const uint32_t*)Pl,
        (const uint32_t*)Wh, (const uint32_t*)Wl,
        (uint32_t*)Qh, (uint32_t*)Ql, (uint32_t*)Kh, (uint32_t*)Kl,
        Vb, (uint32_t*)KPh, (uint32_t*)KPl);

    // 4) fused dpt + cpp (from planes)
    const int total_small = BATCH * HEADS * TLEN + HEADS * P2;
    dptcpp_kernel<<<(total_small + 255) / 256, 256>>>(
        (const uint32_t*)Kh, (const uint32_t*)Kl,
        (const uint32_t*)KPh, (const uint32_t*)KPl,
        parma, parmb, dptb, cppb);

    // 5) attention (bf16x3 ldmatrix scores, tf32x3 PV; writes ATT planes)
    cudaFuncSetAttribute(attn_kernel,
                         cudaFuncAttributeMaxDynamicSharedMemorySize,
                         ATTN_SMEM_BYTES);
    attn_kernel<<<dim3(TLEN / 64, HEADS, BATCH), 256, ATTN_SMEM_BYTES>>>(
        (const uint32_t*)Qh, (const uint32_t*)Ql,
        (const uint32_t*)Kh, (const uint32_t*)Kl,
        Vb, (const uint32_t*)KPh, (const uint32_t*)KPl,
        dptb, cppb, (uint32_t*)ATTh, (uint32_t*)ATTl);

    // 6) output projection (+bias, bf16x3)
    cudaFuncSetAttribute(gemmU_kernel,
                         cudaFuncAttributeMaxDynamicSharedMemorySize,
                         GEMM_SMEM_BYTES);
    gemmU_kernel<<<dim3(8, 32), 256, GEMM_SMEM_BYTES>>>(
        (const uint32_t*)ATTh, (const uint32_t*)ATTl,
        (const uint32_t*)Wh + 4 * (size_t)EDIM * EDIM / 2,
        (const uint32_t*)Wl + 4 * (size_t)EDIM * EDIM / 2,
        bu, out);
}

// round 14
// speedup vs baseline: 1.0054x; 1.0054x over previous
#include <cuda_runtime.h>
#include <cuda_bf16.h>
#include <math.h>
#include <stdint.h>

// Problem constants
#define BATCH 4
#define TLEN  1024
#define EDIM  1024
#define HEADS 16
#define SDIM  64
#define P2    2047   // 2*t - 1

// ---------------------------------------------------------------------------
// Scratch (device globals — no runtime allocation allowed)
// ---------------------------------------------------------------------------
__device__ float g_dpt[(size_t)BATCH * HEADS * TLEN];
__device__ float g_cpp[(size_t)HEADS * P2];
// bf16 hi/lo planes
__device__ __nv_bfloat16 g_Xh [(size_t)BATCH * TLEN * EDIM];
__device__ __nv_bfloat16 g_Xl [(size_t)BATCH * TLEN * EDIM];
__device__ __nv_bfloat16 g_Psrch[(size_t)P2 * EDIM];
__device__ __nv_bfloat16 g_Psrcl[(size_t)P2 * EDIM];
__device__ __nv_bfloat16 g_Wh [(size_t)5 * EDIM * EDIM];  // transposed [N,K]
__device__ __nv_bfloat16 g_Wl [(size_t)5 * EDIM * EDIM];
__device__ __nv_bfloat16 g_Qh [(size_t)BATCH * TLEN * EDIM];
__device__ __nv_bfloat16 g_Ql [(size_t)BATCH * TLEN * EDIM];
__device__ __nv_bfloat16 g_Kh [(size_t)BATCH * TLEN * EDIM];
__device__ __nv_bfloat16 g_Kl [(size_t)BATCH * TLEN * EDIM];
__device__ __nv_bfloat16 g_KPh[(size_t)P2 * EDIM];
__device__ __nv_bfloat16 g_KPl[(size_t)P2 * EDIM];
// V stored TRANSPOSED as planes: [b][h][s][j]
__device__ __nv_bfloat16 g_Vth[(size_t)BATCH * HEADS * SDIM * TLEN];
__device__ __nv_bfloat16 g_Vtl[(size_t)BATCH * HEADS * SDIM * TLEN];
__device__ __nv_bfloat16 g_ATTh[(size_t)BATCH * TLEN * EDIM];
__device__ __nv_bfloat16 g_ATTl[(size_t)BATCH * TLEN * EDIM];

// ---------------------------------------------------------------------------
// helpers
// ---------------------------------------------------------------------------
__device__ __forceinline__ void mma_bf16(float* c,
    uint32_t a0, uint32_t a1, uint32_t a2, uint32_t a3,
    uint32_t b0, uint32_t b1)
{
    asm volatile(
        "mma.sync.aligned.m16n8k16.row.col.f32.bf16.bf16.f32 "
        "{%0,%1,%2,%3}, {%4,%5,%6,%7}, {%8,%9}, {%0,%1,%2,%3};"
        : "+f"(c[0]), "+f"(c[1]), "+f"(c[2]), "+f"(c[3])
        : "r"(a0), "r"(a1), "r"(a2), "r"(a3), "r"(b0), "r"(b1));
}
__device__ __forceinline__ void mma_bf16_x3(float* c,
    const uint32_t* ah, const uint32_t* al,
    uint32_t bh0, uint32_t bh1, uint32_t bl0, uint32_t bl1)
{
    mma_bf16(c, al[0], al[1], al[2], al[3], bh0, bh1);
    mma_bf16(c, ah[0], ah[1], ah[2], ah[3], bl0, bl1);
    mma_bf16(c, ah[0], ah[1], ah[2], ah[3], bh0, bh1);
}
__device__ __forceinline__ void ldm_x4(uint32_t* r, uint32_t saddr) {
    asm volatile(
        "ldmatrix.sync.aligned.m8n8.x4.shared.b16 {%0,%1,%2,%3}, [%4];"
        : "=r"(r[0]), "=r"(r[1]), "=r"(r[2]), "=r"(r[3]) : "r"(saddr));
}
__device__ __forceinline__ void bsplit2(float v0, float v1,
                                        uint32_t& hi, uint32_t& lo)
{
    __nv_bfloat162 h = __float22bfloat162_rn(make_float2(v0, v1));
    float r0 = v0 - __bfloat162float(h.x);
    float r1 = v1 - __bfloat162float(h.y);
    __nv_bfloat162 l = __float22bfloat162_rn(make_float2(r0, r1));
    hi = *(uint32_t*)&h;
    lo = *(uint32_t*)&l;
}
__device__ __forceinline__ void bsplit1(float v, __nv_bfloat16& h,
                                        __nv_bfloat16& l)
{
    h = __float2bfloat16_rn(v);
    l = __float2bfloat16_rn(v - __bfloat162float(h));
}
__device__ __forceinline__ float2 brecon2(uint32_t h, uint32_t l) {
    __nv_bfloat162 hb = *(__nv_bfloat162*)&h;
    __nv_bfloat162 lb = *(__nv_bfloat162*)&l;
    return make_float2(__bfloat162float(hb.x) + __bfloat162float(lb.x),
                       __bfloat162float(hb.y) + __bfloat162float(lb.y));
}

// cp.async helpers (baseline PTX, sm_80+); v=false -> zero-fill 16B
__device__ __forceinline__ void cpa16(void* smem_dst, const void* gsrc, bool v) {
    uint32_t s = (uint32_t)__cvta_generic_to_shared(smem_dst);
    int sz = v ? 16 : 0;
    asm volatile("cp.async.cg.shared.global [%0], [%1], 16, %2;"
                 :: "r"(s), "l"(gsrc), "r"(sz) : "memory");
}
#define CP_COMMIT() asm volatile("cp.async.commit_group;" ::: "memory")
#define CP_WAIT1()  asm volatile("cp.async.wait_group 1;" ::: "memory")
#define CP_WAIT0()  asm volatile("cp.async.wait_group 0;" ::: "memory")

// ---------------------------------------------------------------------------
// Transpose 5 weights into bf16 hi/lo planes
// ---------------------------------------------------------------------------
__global__ void __launch_bounds__(256) transpose5_kernel(
    const float* __restrict__ W0, const float* __restrict__ W1,
    const float* __restrict__ W2, const float* __restrict__ W3,
    const float* __restrict__ W4,
    __nv_bfloat16* __restrict__ dstHi, __nv_bfloat16* __restrict__ dstLo)
{
    __shared__ float t[32][33];
    int z = blockIdx.z;
    const float* src = (z == 0) ? W0 : (z == 1) ? W1 : (z == 2) ? W2
                     : (z == 3) ? W3 : W4;
    size_t base = (size_t)z * EDIM * EDIM;
    int bx = blockIdx.x * 32, by = blockIdx.y * 32;
    int x = threadIdx.x, y = threadIdx.y;   // block (32, 8)
    #pragma unroll
    for (int i = 0; i < 32; i += 8)
        t[y + i][x] = src[(size_t)(by + y + i) * EDIM + bx + x];
    __syncthreads();
    #pragma unroll
    for (int i = 0; i < 32; i += 8) {
        float v = t[x][y + i];
        __nv_bfloat16 hb, lb;
        bsplit1(v, hb, lb);
        size_t o = base + (size_t)(bx + y + i) * EDIM + by + x;
        dstHi[o] = hb;
        dstLo[o] = lb;
    }
}

// ---------------------------------------------------------------------------
// Convert fp32 array to bf16 hi/lo planes (pairwise)
// ---------------------------------------------------------------------------
__global__ void __launch_bounds__(256) cvt_planes_kernel(
    const float2* __restrict__ src, uint32_t* __restrict__ hi,
    uint32_t* __restrict__ lo, int npairs)
{
    int i = blockIdx.x * 256 + threadIdx.x;
    if (i >= npairs) return;
    float2 v = src[i];
    uint32_t h, l;
    bsplit2(v.x, v.y, h, l);
    hi[i] = h;
    lo[i] = l;
}

// ---------------------------------------------------------------------------
// bf16x3 tensor-core GEMM tile with ldmatrix fragment loads.
// Epilogue modes: fp32(+bias), row-major planes, or transposed V planes.
// ---------------------------------------------------------------------------
#define GPW 20                         // uint32 words per smem plane row
#define PLANE_W (128 * GPW)            // 2560 words per plane
#define GEMM_SMEM_BYTES (8 * PLANE_W * 4)   // 81920 B

__device__ __forceinline__ void gemm_stage_bf16(
    uint32_t* s,
    const uint32_t* __restrict__ Ah, const uint32_t* __restrict__ Al,
    const uint32_t* __restrict__ Bh, const uint32_t* __restrict__ Bl,
    int M, int bm, int bn, int koffw, int tid)
{
    #pragma unroll
    for (int r = 0; r < 2; r++) {
        int slot = tid + 256 * r;          // 0..511
        int row = slot >> 2, ch = (slot & 3) * 4;
        int grow = bm + row;
        bool v = grow < M;
        size_t ga = (size_t)(v ? grow : 0) * 512 + koffw + ch;
        size_t gb = (size_t)(bn + row) * 512 + koffw + ch;
        uint32_t* sd = s + row * GPW + ch;
        cpa16(sd,               &Ah[ga], v);
        cpa16(sd + PLANE_W,     &Al[ga], v);
        cpa16(sd + 2 * PLANE_W, &Bh[gb], true);
        cpa16(sd + 3 * PLANE_W, &Bl[gb], true);
    }
    CP_COMMIT();
}

__device__ __forceinline__ void gemm_tile(
    const uint32_t* __restrict__ Ah, const uint32_t* __restrict__ Al,
    const uint32_t* __restrict__ Bh, const uint32_t* __restrict__ Bl,
    const float* __restrict__ bias, float* __restrict__ Cf,
    uint32_t* __restrict__ Ch, uint32_t* __restrict__ Cl,
    __nv_bfloat16* __restrict__ VtH, __nv_bfloat16* __restrict__ VtL,
    int M, int hasBias, int bm, int bn)
{
    extern __shared__ uint32_t gsm[];
    uint32_t* buf0 = gsm;
    uint32_t* buf1 = gsm + 4 * PLANE_W;

    const int tid  = threadIdx.x;
    const int wid  = tid >> 5;
    const int lane = tid & 31;
    const int wm = wid & 1;
    const int wn = wid >> 1;
    const int g = lane >> 2;
    const int t = lane & 3;
    const uint32_t lz = (((lane & 15) * GPW) + ((lane >> 4) << 2)) * 4;
    const uint32_t smem0 = (uint32_t)__cvta_generic_to_shared(gsm);

    gemm_stage_bf16(buf0, Ah, Al, Bh, Bl, M, bm, bn, 0,  tid);
    gemm_stage_bf16(buf1, Ah, Al, Bh, Bl, M, bm, bn, 16, tid);

    float acc[4][4][4];
    #pragma unroll
    for (int mi = 0; mi < 4; mi++)
        #pragma unroll
        for (int ni = 0; ni < 4; ni++)
            #pragma unroll
            for (int q = 0; q < 4; q++) acc[mi][ni][q] = 0.f;

    #pragma unroll 1
    for (int kt = 0; kt < 32; kt++) {
        if (kt + 1 < 32) CP_WAIT1(); else CP_WAIT0();
        __syncthreads();
        const uint32_t bufo = (kt & 1) ? (4 * PLANE_W * 4) : 0;
        const uint32_t aho = smem0 + bufo + lz;
        const uint32_t alo = aho + PLANE_W * 4;
        const uint32_t bho = alo + PLANE_W * 4;
        const uint32_t blo = bho + PLANE_W * 4;

        #pragma unroll
        for (int ks = 0; ks < 2; ks++) {
            const uint32_t kbB = (uint32_t)(ks * 8) * 4;
            uint32_t ah[4][4], al[4][4], bh[2][4], bl[2][4];
            #pragma unroll
            for (int mi = 0; mi < 4; mi++) {
                uint32_t ro = (uint32_t)((wm * 64 + mi * 16) * GPW) * 4 + kbB;
                ldm_x4(ah[mi], aho + ro);
                ldm_x4(al[mi], alo + ro);
            }
            #pragma unroll
            for (int p = 0; p < 2; p++) {
                uint32_t ro = (uint32_t)((wn * 32 + p * 16) * GPW) * 4 + kbB;
                ldm_x4(bh[p], bho + ro);
                ldm_x4(bl[p], blo + ro);
            }
            #pragma unroll
            for (int ni = 0; ni < 4; ni++) {
                int p = ni >> 1, o = ni & 1;
                uint32_t bh0 = bh[p][o], bh1 = bh[p][o + 2];
                uint32_t bl0 = bl[p][o], bl1 = bl[p][o + 2];
                #pragma unroll
                for (int mi = 0; mi < 4; mi++)
                    mma_bf16_x3(acc[mi][ni], ah[mi], al[mi], bh0, bh1, bl0, bl1);
            }
        }
        __syncthreads();
        if (kt + 2 < 32)
            gemm_stage_bf16((kt & 1) ? buf1 : buf0, Ah, Al, Bh, Bl,
                            M, bm, bn, (kt + 2) * 16, tid);
    }

    #pragma unroll
    for (int mi = 0; mi < 4; mi++) {
        int row0 = bm + wm * 64 + mi * 16 + g;
        #pragma unroll
        for (int ni = 0; ni < 4; ni++) {
            int col = bn + wn * 32 + ni * 8 + t * 2;
            if (Cf) {
                float b0 = hasBias ? bias[col] : 0.f;
                float b1 = hasBias ? bias[col + 1] : 0.f;
                if (row0 < M) {
                    Cf[(size_t)row0 * EDIM + col]     = acc[mi][ni][0] + b0;
                    Cf[(size_t)row0 * EDIM + col + 1] = acc[mi][ni][1] + b1;
                }
                if (row0 + 8 < M) {
                    Cf[(size_t)(row0 + 8) * EDIM + col]     = acc[mi][ni][2] + b0;
                    Cf[(size_t)(row0 + 8) * EDIM + col + 1] = acc[mi][ni][3] + b1;
                }
            } else if (Ch) {
                uint32_t h, l;
                if (row0 < M) {
                    bsplit2(acc[mi][ni][0], acc[mi][ni][1], h, l);
                    size_t w = (size_t)row0 * 512 + (col >> 1);
                    Ch[w] = h; Cl[w] = l;
                }
                if (row0 + 8 < M) {
                    bsplit2(acc[mi][ni][2], acc[mi][ni][3], h, l);
                    size_t w = (size_t)(row0 + 8) * 512 + (col >> 1);
                    Ch[w] = h; Cl[w] = l;
                }
            } else {
                // transposed V planes: dst[(b*16+h)*64+s][j]
                int bb = row0 >> 10, j = row0 & (TLEN - 1);
                size_t r0a = ((size_t)(bb * HEADS + (col >> 6)) * 64
                              + (col & 63)) * TLEN;
                size_t r1a = r0a + TLEN;   // col+1 -> s+1 (col is even)
                __nv_bfloat16 hh, ll;
                bsplit1(acc[mi][ni][0], hh, ll);
                VtH[r0a + j] = hh;     VtL[r0a + j] = ll;
                bsplit1(acc[mi][ni][2], hh, ll);
                VtH[r0a + j + 8] = hh; VtL[r0a + j + 8] = ll;
                bsplit1(acc[mi][ni][1], hh, ll);
                VtH[r1a + j] = hh;     VtL[r1a + j] = ll;
                bsplit1(acc[mi][ni][3], hh, ll);
                VtH[r1a + j + 8] = hh; VtL[r1a + j + 8] = ll;
            }
        }
    }
}

// Fused projections: z=0 Q planes, z=1 K planes, z=2 V^T planes, z=3 KP planes.
__global__ void __launch_bounds__(256, 2) fused_gemm_kernel(
    const uint32_t* __restrict__ Xh, const uint32_t* __restrict__ Xl,
    const uint32_t* __restrict__ Ph, const uint32_t* __restrict__ Pl,
    const uint32_t* __restrict__ Wh, const uint32_t* __restrict__ Wl,
    uint32_t* __restrict__ Qh, uint32_t* __restrict__ Ql,
    uint32_t* __restrict__ Kh, uint32_t* __restrict__ Kl,
    __nv_bfloat16* __restrict__ Vth, __nv_bfloat16* __restrict__ Vtl,
    uint32_t* __restrict__ KPh, uint32_t* __restrict__ KPl)
{
    const int z = blockIdx.z;
    const uint32_t* Ah = (z < 3) ? Xh : Ph;
    const uint32_t* Al = (z < 3) ? Xl : Pl;
    const int M = (z < 3) ? (BATCH * TLEN) : P2;
    const int bm = blockIdx.y * 128;
    if (bm >= M) return;
    const uint32_t* Bh = Wh + (size_t)z * EDIM * EDIM / 2;
    const uint32_t* Bl = Wl + (size_t)z * EDIM * EDIM / 2;
    uint32_t* Ch = (z == 0) ? Qh : (z == 1) ? Kh : (z == 3) ? KPh : nullptr;
    uint32_t* Cl = (z == 0) ? Ql : (z == 1) ? Kl : (z == 3) ? KPl : nullptr;
    __nv_bfloat16* VtH = (z == 2) ? Vth : nullptr;
    __nv_bfloat16* VtL = (z == 2) ? Vtl : nullptr;
    gemm_tile(Ah, Al, Bh, Bl, nullptr, nullptr, Ch, Cl, VtH, VtL,
              M, 0, bm, blockIdx.x * 128);
}

__global__ void __launch_bounds__(256, 2) gemmU_kernel(
    const uint32_t* __restrict__ Ah, const uint32_t* __restrict__ Al,
    const uint32_t* __restrict__ Bh, const uint32_t* __restrict__ Bl,
    const float* __restrict__ bias, float* __restrict__ C)
{
    gemm_tile(Ah, Al, Bh, Bl, bias, C, nullptr, nullptr, nullptr, nullptr,
              BATCH * TLEN, 1, blockIdx.y * 128, blockIdx.x * 128);
}

// ---------------------------------------------------------------------------
// Fused dpt + cpp (reads bf16 planes, reconstructs hi+lo)
// ---------------------------------------------------------------------------
__global__ void __launch_bounds__(256) dptcpp_kernel(
    const uint32_t* __restrict__ Kh, const uint32_t* __restrict__ Kl,
    const uint32_t* __restrict__ KPh, const uint32_t* __restrict__ KPl,
    const float* __restrict__ parma, const float* __restrict__ parmb,
    float* __restrict__ dpt, float* __restrict__ cpp)
{
    int idx = blockIdx.x * 256 + threadIdx.x;
    if (idx < BATCH * HEADS * TLEN) {
        int j = idx & (TLEN - 1);
        int h = (idx >> 10) & (HEADS - 1);
        int b = idx >> 14;
        size_t base = (size_t)(b * TLEN + j) * 512 + h * 32;
        const float* pa = parma + h * SDIM;
        float s = 0.f;
        #pragma unroll
        for (int w = 0; w < 32; w++) {
            float2 f = brecon2(Kh[base + w], Kl[base + w]);
            s = fmaf(pa[2 * w], f.x, s);
            s = fmaf(pa[2 * w + 1], f.y, s);
        }
        dpt[idx] = s;
    } else {
        int i2 = idx - BATCH * HEADS * TLEN;
        if (i2 >= HEADS * P2) return;
        int h = i2 / P2;
        int p = i2 - h * P2;
        size_t base = (size_t)p * 512 + h * 32;
        const float* pb = parmb + h * SDIM;
        float s = 0.f;
        #pragma unroll
        for (int w = 0; w < 32; w++) {
            float2 f = brecon2(KPh[base + w], KPl[base + w]);
            s = fmaf(pb[2 * w], f.x, s);
            s = fmaf(pb[2 * w + 1], f.y, s);
        }
        cpp[i2] = s;
    }
}

// ---------------------------------------------------------------------------
// Tensor-core attention: all mma bf16x3 (k16, ldmatrix) on hi/lo planes.
// Scores: Q @ [K;KPband]^T band-masked. PV: P planes @ Vt planes.
// ---------------------------------------------------------------------------
#define QW 36    // word stride for plane rows
#define SP 196   // S matrix stride (floats)

// word offsets
#define OFF_QH 0
#define OFF_QL 2304
#define OFF_BH 4608
#define OFF_BL 11520
#define OFF_VTH 18432
#define OFF_VTL 20736
#define OFF_PH 23040
#define OFF_PL 25344
#define OFF_DP 27648
#define OFF_CP 27712
#define OFF_SC 27840
#define OFF_LS 27904
#define ATTN_SMEM_BYTES (27968 * 4)

__global__ void __launch_bounds__(256, 2) attn_kernel(
    const uint32_t* __restrict__ Qh, const uint32_t* __restrict__ Ql,
    const uint32_t* __restrict__ Kh, const uint32_t* __restrict__ Kl,
    const uint32_t* __restrict__ Vth, const uint32_t* __restrict__ Vtl,
    const uint32_t* __restrict__ KPh, const uint32_t* __restrict__ KPl,
    const float* __restrict__ dpt, const float* __restrict__ cpp,
    uint32_t* __restrict__ Oh, uint32_t* __restrict__ Ol)
{
    extern __shared__ uint32_t smw[];
    uint32_t* Qhs = smw + OFF_QH;       // [64][QW]
    uint32_t* Qls = smw + OFF_QL;
    uint32_t* Bhs = smw + OFF_BH;       // [192][QW]
    uint32_t* Bls = smw + OFF_BL;
    float* Ssm  = (float*)(smw + OFF_BH);   // [64][SP] aliases B planes
    uint32_t* Vths = smw + OFF_VTH;     // [64 s][QW]
    uint32_t* Vtls = smw + OFF_VTL;
    __nv_bfloat16* PH = (__nv_bfloat16*)(smw + OFF_PH);  // [64][72]
    __nv_bfloat16* PL = (__nv_bfloat16*)(smw + OFF_PL);
    float* dpts = (float*)(smw + OFF_DP);
    float* cpps = (float*)(smw + OFF_CP);
    float* scale_sm = (float*)(smw + OFF_SC);
    float* lsum_sm  = (float*)(smw + OFF_LS);

    const int tid  = threadIdx.x;
    const int lane = tid & 31;
    const int wid  = tid >> 5;
    const int g = lane >> 2;
    const int t = lane & 3;
    const int rm = (wid & 1) * 32;      // scores m-base
    const int cn = (wid >> 1) * 48;     // scores n-base
    const int sm0 = (wid & 3) * 16;     // PV m-slice
    const int pn0 = (wid >> 2) * 32;    // PV n-slice
    const int tx = tid & 15, ty = tid >> 4;
    const uint32_t lzq = (((lane & 15) * QW) + ((lane >> 4) << 2)) * 4;
    const uint32_t smb = (uint32_t)__cvta_generic_to_shared(smw);

    const int b = blockIdx.z, h = blockIdx.y;
    const int it = (int)gridDim.x - 1 - (int)blockIdx.x;
    const int I0 = it * 64;
    const int hw = h * 32;

    // Stage Q planes once
    for (int idx = tid; idx < 512; idx += 256) {
        int r = idx >> 3, w = (idx & 7) * 4;
        size_t gq = (size_t)(b * TLEN + I0 + r) * 512 + hw + w;
        cpa16(&Qhs[r * QW + w], &Qh[gq], true);
        cpa16(&Qls[r * QW + w], &Ql[gq], true);
    }
    CP_COMMIT();

    float m_r[4], l_r[4];
    #pragma unroll
    for (int i = 0; i < 4; i++) { m_r[i] = -INFINITY; l_r[i] = 0.f; }
    float o_acc[4][4];
    #pragma unroll
    for (int n = 0; n < 4; n++)
        #pragma unroll
        for (int q = 0; q < 4; q++) o_acc[n][q] = 0.f;

    for (int jt = 0; jt <= it; jt++) {
        const int J0 = jt * 64;
        const int pbase = I0 + J0;
        const int d = I0 - J0;

        __syncthreads();

        // ---- Stage K planes, KP planes, Vt planes ----
        for (int idx = tid; idx < 512; idx += 256) {
            int c = idx >> 3, w = (idx & 7) * 4;
            size_t gk = (size_t)(b * TLEN + J0 + c) * 512 + hw + w;
            cpa16(&Bhs[c * QW + w], &Kh[gk], true);
            cpa16(&Bls[c * QW + w], &Kl[gk], true);
        }
        for (int idx = tid; idx < 1024; idx += 256) {
            int pl = idx >> 3, w = (idx & 7) * 4;
            int p = pbase + pl;
            bool v = p < P2;
            size_t gp = (size_t)(v ? p : 0) * 512 + hw + w;
            cpa16(&Bhs[(64 + pl) * QW + w], &KPh[gp], v);
            cpa16(&Bls[(64 + pl) * QW + w], &KPl[gp], v);
        }
        for (int idx = tid; idx < 512; idx += 256) {
            int s = idx >> 3, w = (idx & 7) * 4;
            size_t gv = ((size_t)((b * HEADS + h) * 64 + s)) * 512
                      + (J0 >> 1) + w;
            cpa16(&Vths[s * QW + w], &Vth[gv], true);
            cpa16(&Vtls[s * QW + w], &Vtl[gv], true);
        }
        CP_COMMIT();
        if (tid < 64) dpts[tid] = dpt[((size_t)(b * HEADS + h)) * TLEN + J0 + tid];
        if (tid < 128) {
            int p = pbase + tid;
            cpps[tid] = (p < P2) ? cpp[(size_t)h * P2 + p] : 0.f;
        }
        CP_WAIT0();
        __syncthreads();

        // Fragment need-masks (warp-uniform)
        bool need[2][6];
        #pragma unroll
        for (int mi = 0; mi < 2; mi++) {
            int m0 = rm + 16 * mi;
            int cmax = m0 + 15 + d; if (cmax > 63) cmax = 63;
            #pragma unroll
            for (int nt = 0; nt < 6; nt++) {
                int n0 = cn + nt * 8;
                if (n0 < 64) {
                    need[mi][nt] = (n0 <= m0 + 15 + d);
                } else {
                    int pl0 = n0 - 64;
                    need[mi][nt] = (pl0 + 7 >= m0) && (pl0 <= m0 + 15 + cmax);
                }
            }
        }

        // ---- Scores mma: bf16x3 m16n8k16 via ldmatrix ----
        float sacc[2][6][4];
        #pragma unroll
        for (int mi = 0; mi < 2; mi++)
            #pragma unroll
            for (int n = 0; n < 6; n++)
                #pragma unroll
                for (int q = 0; q < 4; q++) sacc[mi][n][q] = 0.f;

        const uint32_t qh0 = smb + OFF_QH * 4 + lzq;
        const uint32_t ql0 = smb + OFF_QL * 4 + lzq;
        const uint32_t bh0b = smb + OFF_BH * 4 + lzq;
        const uint32_t bl0b = smb + OFF_BL * 4 + lzq;

        #pragma unroll
        for (int kc = 0; kc < 4; kc++) {
            const uint32_t kbB = (uint32_t)(kc * 8) * 4;
            uint32_t ah[2][4], al[2][4], bh[3][4], bl[3][4];
            #pragma unroll
            for (int mi = 0; mi < 2; mi++) {
                uint32_t ro = (uint32_t)((rm + 16 * mi) * QW) * 4 + kbB;
                ldm_x4(ah[mi], qh0 + ro);
                ldm_x4(al[mi], ql0 + ro);
            }
            #pragma unroll
            for (int p = 0; p < 3; p++) {
                uint32_t ro = (uint32_t)((cn + p * 16) * QW) * 4 + kbB;
                ldm_x4(bh[p], bh0b + ro);
                ldm_x4(bl[p], bl0b + ro);
            }
            #pragma unroll
            for (int nt = 0; nt < 6; nt++) {
                if (!need[0][nt] && !need[1][nt]) continue;
                int p = nt >> 1, o = nt & 1;
                uint32_t b0 = bh[p][o], b1 = bh[p][o + 2];
                uint32_t c0 = bl[p][o], c1 = bl[p][o + 2];
                if (need[0][nt])
                    mma_bf16_x3(sacc[0][nt], ah[0], al[0], b0, b1, c0, c1);
                if (need[1][nt])
                    mma_bf16_x3(sacc[1][nt], ah[1], al[1], b0, b1, c0, c1);
            }
        }

        __syncthreads();   // done reading B planes; overwrite as Ssm
        #pragma unroll
        for (int mi = 0; mi < 2; mi++) {
            int r0 = rm + 16 * mi + g;
            #pragma unroll
            for (int nt = 0; nt < 6; nt++) {
                if (!need[mi][nt]) continue;
                int n0 = cn + nt * 8 + 2 * t;
                Ssm[r0 * SP + n0]           = sacc[mi][nt][0];
                Ssm[r0 * SP + n0 + 1]       = sacc[mi][nt][1];
                Ssm[(r0 + 8) * SP + n0]     = sacc[mi][nt][2];
                Ssm[(r0 + 8) * SP + n0 + 1] = sacc[mi][nt][3];
            }
        }
        __syncthreads();

        // ---- Softmax (fp32 SIMT), P written as bf16 hi/lo planes ----
        #pragma unroll
        for (int i = 0; i < 4; i++) {
            int r = ty + 16 * i;
            float sc[4];
            float mx = -INFINITY;
            #pragma unroll
            for (int j = 0; j < 4; j++) {
                int c = tx + 16 * j;
                float v = Ssm[r * SP + c] + Ssm[r * SP + 64 + r + c]
                        + dpts[c] + cpps[r + c];
                if (c > r + d) v = -1e30f;
                sc[j] = v;
                mx = fmaxf(mx, v);
            }
            #pragma unroll
            for (int off = 8; off >= 1; off >>= 1)
                mx = fmaxf(mx, __shfl_xor_sync(0xffffffffu, mx, off));
            float mnew = fmaxf(m_r[i], mx);
            float scale = __expf(m_r[i] - mnew);
            m_r[i] = mnew;
            float rs = 0.f;
            #pragma unroll
            for (int j = 0; j < 4; j++) {
                float p = __expf(sc[j] - mnew);
                int c = tx + 16 * j;
                __nv_bfloat16 hb, lb;
                bsplit1(p, hb, lb);
                PH[r * 72 + c] = hb;
                PL[r * 72 + c] = lb;
                rs += p;
            }
            #pragma unroll
            for (int off = 8; off >= 1; off >>= 1)
                rs += __shfl_xor_sync(0xffffffffu, rs, off);
            l_r[i] = l_r[i] * scale + rs;
            if (tx == 0) {
                scale_sm[r] = scale;
                lsum_sm[r]  = l_r[i];
            }
        }
        __syncthreads();

        // ---- PV mma: O = O*scale + P @ Vt^T (bf16x3, ldmatrix) ----
        const float sA = scale_sm[sm0 + g];
        const float sB = scale_sm[sm0 + g + 8];
        #pragma unroll
        for (int nt = 0; nt < 4; nt++) {
            o_acc[nt][0] *= sA; o_acc[nt][1] *= sA;
            o_acc[nt][2] *= sB; o_acc[nt][3] *= sB;
        }
        const uint32_t ph0 = smb + OFF_PH * 4 + lzq;
        const uint32_t pl0b = smb + OFF_PL * 4 + lzq;
        const uint32_t vh0 = smb + OFF_VTH * 4 + lzq;
        const uint32_t vl0 = smb + OFF_VTL * 4 + lzq;
        #pragma unroll
        for (int kc = 0; kc < 4; kc++) {
            const uint32_t kbB = (uint32_t)(kc * 8) * 4;
            uint32_t ah[4], al[4], bh[2][4], bl[2][4];
            {
                uint32_t ro = (uint32_t)(sm0 * QW) * 4 + kbB;
                ldm_x4(ah, ph0 + ro);
                ldm_x4(al, pl0b + ro);
            }
            #pragma unroll
            for (int p = 0; p < 2; p++) {
                uint32_t ro = (uint32_t)((pn0 + p * 16) * QW) * 4 + kbB;
                ldm_x4(bh[p], vh0 + ro);
                ldm_x4(bl[p], vl0 + ro);
            }
            #pragma unroll
            for (int nt = 0; nt < 4; nt++) {
                int p = nt >> 1, o = nt & 1;
                mma_bf16_x3(o_acc[nt], ah, al,
                            bh[p][o], bh[p][o + 2], bl[p][o], bl[p][o + 2]);
            }
        }
    }

    __syncthreads();
    const float invA = 1.f / lsum_sm[sm0 + g];
    const float invB = 1.f / lsum_sm[sm0 + g + 8];
    const size_t row0 = (size_t)(b * TLEN + I0 + sm0 + g) * EDIM;
    const size_t row1 = row0 + 8 * EDIM;
    #pragma unroll
    for (int nt = 0; nt < 4; nt++) {
        size_t col = (size_t)h * SDIM + pn0 + nt * 8 + 2 * t;   // even
        uint32_t hA, lA, hB, lB;
        bsplit2(o_acc[nt][0] * invA, o_acc[nt][1] * invA, hA, lA);
        bsplit2(o_acc[nt][2] * invB, o_acc[nt][3] * invB, hB, lB);
        Oh[(row0 + col) >> 1] = hA;
        Ol[(row0 + col) >> 1] = lA;
        Oh[(row1 + col) >> 1] = hB;
        Ol[(row1 + col) >> 1] = lB;
    }
}

// ---------------------------------------------------------------------------
// Launch
// ---------------------------------------------------------------------------
extern "C" void kernel_launch(void* const* d_in, const int* in_sizes, int n_in,
                              void* d_out, int out_size)
{
    const float* x     = (const float*)d_in[0];
    const float* Wq    = (const float*)d_in[1];
    const float* Wk    = (const float*)d_in[2];
    const float* Wkp   = (const float*)d_in[3];
    const float* Wv    = (const float*)d_in[4];
    const float* Wu    = (const float*)d_in[5];
    const float* bu    = (const float*)d_in[6];
    const float* parma = (const float*)d_in[7];
    const float* parmb = (const float*)d_in[8];
    const float* pos   = (const float*)d_in[9];
    float* out = (float*)d_out;

    float *dptb, *cppb;
    void *Xh, *Xl, *Ph, *Pl, *Wh, *Wl, *Qh, *Ql, *Kh, *Kl, *KPh, *KPl;
    void *Vth, *Vtl, *ATTh, *ATTl;
    cudaGetSymbolAddress((void**)&dptb, g_dpt);
    cudaGetSymbolAddress((void**)&cppb, g_cpp);
    cudaGetSymbolAddress(&Xh,  g_Xh);
    cudaGetSymbolAddress(&Xl,  g_Xl);
    cudaGetSymbolAddress(&Ph,  g_Psrch);
    cudaGetSymbolAddress(&Pl,  g_Psrcl);
    cudaGetSymbolAddress(&Wh,  g_Wh);
    cudaGetSymbolAddress(&Wl,  g_Wl);
    cudaGetSymbolAddress(&Qh,  g_Qh);
    cudaGetSymbolAddress(&Ql,  g_Ql);
    cudaGetSymbolAddress(&Kh,  g_Kh);
    cudaGetSymbolAddress(&Kl,  g_Kl);
    cudaGetSymbolAddress(&KPh, g_KPh);
    cudaGetSymbolAddress(&KPl, g_KPl);
    cudaGetSymbolAddress(&Vth, g_Vth);
    cudaGetSymbolAddress(&Vtl, g_Vtl);
    cudaGetSymbolAddress(&ATTh, g_ATTh);
    cudaGetSymbolAddress(&ATTl, g_ATTl);

    // 1) transpose + split weights into bf16 planes
    transpose5_kernel<<<dim3(32, 32, 5), dim3(32, 8)>>>(
        Wq, Wk, Wv, Wkp, Wu, (__nv_bfloat16*)Wh, (__nv_bfloat16*)Wl);

    // 2) split x and pos into planes
    const int xpairs = BATCH * TLEN * EDIM / 2;
    const int ppairs = P2 * EDIM / 2;
    cvt_planes_kernel<<<(xpairs + 255) / 256, 256>>>(
        (const float2*)x, (uint32_t*)Xh, (uint32_t*)Xl, xpairs);
    cvt_planes_kernel<<<(ppairs + 255) / 256, 256>>>(
        (const float2*)pos, (uint32_t*)Ph, (uint32_t*)Pl, ppairs);

    // 3) fused projections: Q/K/KP -> planes, V -> transposed planes
    cudaFuncSetAttribute(fused_gemm_kernel,
                         cudaFuncAttributeMaxDynamicSharedMemorySize,
                         GEMM_SMEM_BYTES);
    fused_gemm_kernel<<<dim3(8, 32, 4), 256, GEMM_SMEM_BYTES>>>(
        (const uint32_t*)Xh, (const uint32_t*)Xl,
        (const uint32_t*)Ph, (const uint32_t*)Pl,
        (const uint32_t*)Wh, (const uint32_t*)Wl,
        (uint32_t*)Qh, (uint32_t*)Ql, (uint32_t*)Kh, (uint32_t*)Kl,
        (__nv_bfloat16*)Vth, (__nv_bfloat16*)Vtl,
        (uint32_t*)KPh, (uint32_t*)KPl);

    // 4) fused dpt + cpp (from planes)
    const int total_small = BATCH * HEADS * TLEN + HEADS * P2;
    dptcpp_kernel<<<(total_small + 255) / 256, 256>>>(
        (const uint32_t*)Kh, (const uint32_t*)Kl,
        (const uint32_t*)KPh, (const uint32_t*)KPl,
        parma, parmb, dptb, cppb);

    // 5) attention (all-bf16x3; writes ATT planes)
    cudaFuncSetAttribute(attn_kernel,
                         cudaFuncAttributeMaxDynamicSharedMemorySize,
                         ATTN_SMEM_BYTES);
    attn_kernel<<<dim3(TLEN / 64, HEADS, BATCH), 256, ATTN_SMEM_BYTES>>>(
        (const uint32_t*)Qh, (const uint32_t*)Ql,
        (const uint32_t*)Kh, (const uint32_t*)Kl,
        (const uint32_t*)Vth, (const uint32_t*)Vtl,
        (const uint32_t*)KPh, (const uint32_t*)KPl,
        dptb, cppb, (uint32_t*)ATTh, (uint32_t*)ATTl);

    // 6) output projection (+bias, bf16x3)
    cudaFuncSetAttribute(gemmU_kernel,
                         cudaFuncAttributeMaxDynamicSharedMemorySize,
                         GEMM_SMEM_BYTES);
    gemmU_kernel<<<dim3(8, 32), 256, GEMM_SMEM_BYTES>>>(
        (const uint32_t*)ATTh, (const uint32_t*)ATTl,
        (const uint32_t*)Wh + 4 * (size_t)EDIM * EDIM / 2,
        (const uint32_t*)Wl + 4 * (size_t)EDIM * EDIM / 2,
        bu, out);
}

// round 15
// speedup vs baseline: 1.0193x; 1.0138x over previous
#include <cuda_runtime.h>
#include <cuda_bf16.h>
#include <math.h>
#include <stdint.h>

// Problem constants
#define BATCH 4
#define TLEN  1024
#define EDIM  1024
#define HEADS 16
#define SDIM  64
#define P2    2047   // 2*t - 1

// ---------------------------------------------------------------------------
// Scratch (device globals — no runtime allocation allowed)
// ---------------------------------------------------------------------------
__device__ float g_dpt[(size_t)BATCH * HEADS * TLEN];
__device__ float g_cpp[(size_t)HEADS * P2];
// bf16 hi/lo planes
__device__ __nv_bfloat16 g_Xh [(size_t)BATCH * TLEN * EDIM];
__device__ __nv_bfloat16 g_Xl [(size_t)BATCH * TLEN * EDIM];
__device__ __nv_bfloat16 g_Psrch[(size_t)P2 * EDIM];
__device__ __nv_bfloat16 g_Psrcl[(size_t)P2 * EDIM];
__device__ __nv_bfloat16 g_Wh [(size_t)5 * EDIM * EDIM];  // transposed [N,K]
__device__ __nv_bfloat16 g_Wl [(size_t)5 * EDIM * EDIM];
__device__ __nv_bfloat16 g_Qh [(size_t)BATCH * TLEN * EDIM];
__device__ __nv_bfloat16 g_Ql [(size_t)BATCH * TLEN * EDIM];
__device__ __nv_bfloat16 g_Kh [(size_t)BATCH * TLEN * EDIM];
__device__ __nv_bfloat16 g_Kl [(size_t)BATCH * TLEN * EDIM];
__device__ __nv_bfloat16 g_KPh[(size_t)P2 * EDIM];
__device__ __nv_bfloat16 g_KPl[(size_t)P2 * EDIM];
// V stored TRANSPOSED as planes: [b][h][s][j]
__device__ __nv_bfloat16 g_Vth[(size_t)BATCH * HEADS * SDIM * TLEN];
__device__ __nv_bfloat16 g_Vtl[(size_t)BATCH * HEADS * SDIM * TLEN];
__device__ __nv_bfloat16 g_ATTh[(size_t)BATCH * TLEN * EDIM];
__device__ __nv_bfloat16 g_ATTl[(size_t)BATCH * TLEN * EDIM];

// ---------------------------------------------------------------------------
// helpers
// ---------------------------------------------------------------------------
__device__ __forceinline__ void mma_bf16(float* c,
    uint32_t a0, uint32_t a1, uint32_t a2, uint32_t a3,
    uint32_t b0, uint32_t b1)
{
    asm volatile(
        "mma.sync.aligned.m16n8k16.row.col.f32.bf16.bf16.f32 "
        "{%0,%1,%2,%3}, {%4,%5,%6,%7}, {%8,%9}, {%0,%1,%2,%3};"
        : "+f"(c[0]), "+f"(c[1]), "+f"(c[2]), "+f"(c[3])
        : "r"(a0), "r"(a1), "r"(a2), "r"(a3), "r"(b0), "r"(b1));
}
__device__ __forceinline__ void mma_bf16_x3(float* c,
    const uint32_t* ah, const uint32_t* al,
    uint32_t bh0, uint32_t bh1, uint32_t bl0, uint32_t bl1)
{
    mma_bf16(c, al[0], al[1], al[2], al[3], bh0, bh1);
    mma_bf16(c, ah[0], ah[1], ah[2], ah[3], bl0, bl1);
    mma_bf16(c, ah[0], ah[1], ah[2], ah[3], bh0, bh1);
}
__device__ __forceinline__ void ldm_x4(uint32_t* r, uint32_t saddr) {
    asm volatile(
        "ldmatrix.sync.aligned.m8n8.x4.shared.b16 {%0,%1,%2,%3}, [%4];"
        : "=r"(r[0]), "=r"(r[1]), "=r"(r[2]), "=r"(r[3]) : "r"(saddr));
}
__device__ __forceinline__ void bsplit2(float v0, float v1,
                                        uint32_t& hi, uint32_t& lo)
{
    __nv_bfloat162 h = __float22bfloat162_rn(make_float2(v0, v1));
    float r0 = v0 - __bfloat162float(h.x);
    float r1 = v1 - __bfloat162float(h.y);
    __nv_bfloat162 l = __float22bfloat162_rn(make_float2(r0, r1));
    hi = *(uint32_t*)&h;
    lo = *(uint32_t*)&l;
}
__device__ __forceinline__ void bsplit1(float v, __nv_bfloat16& h,
                                        __nv_bfloat16& l)
{
    h = __float2bfloat16_rn(v);
    l = __float2bfloat16_rn(v - __bfloat162float(h));
}
__device__ __forceinline__ float2 brecon2(uint32_t h, uint32_t l) {
    __nv_bfloat162 hb = *(__nv_bfloat162*)&h;
    __nv_bfloat162 lb = *(__nv_bfloat162*)&l;
    return make_float2(__bfloat162float(hb.x) + __bfloat162float(lb.x),
                       __bfloat162float(hb.y) + __bfloat162float(lb.y));
}

// cp.async helpers (baseline PTX, sm_80+); v=false -> zero-fill 16B
__device__ __forceinline__ void cpa16(void* smem_dst, const void* gsrc, bool v) {
    uint32_t s = (uint32_t)__cvta_generic_to_shared(smem_dst);
    int sz = v ? 16 : 0;
    asm volatile("cp.async.cg.shared.global [%0], [%1], 16, %2;"
                 :: "r"(s), "l"(gsrc), "r"(sz) : "memory");
}
#define CP_COMMIT() asm volatile("cp.async.commit_group;" ::: "memory")
#define CP_WAIT1()  asm volatile("cp.async.wait_group 1;" ::: "memory")
#define CP_WAIT0()  asm volatile("cp.async.wait_group 0;" ::: "memory")

// ---------------------------------------------------------------------------
// Transpose 5 weights into bf16 hi/lo planes
// ---------------------------------------------------------------------------
__global__ void __launch_bounds__(256) transpose5_kernel(
    const float* __restrict__ W0, const float* __restrict__ W1,
    const float* __restrict__ W2, const float* __restrict__ W3,
    const float* __restrict__ W4,
    __nv_bfloat16* __restrict__ dstHi, __nv_bfloat16* __restrict__ dstLo)
{
    __shared__ float t[32][33];
    int z = blockIdx.z;
    const float* src = (z == 0) ? W0 : (z == 1) ? W1 : (z == 2) ? W2
                     : (z == 3) ? W3 : W4;
    size_t base = (size_t)z * EDIM * EDIM;
    int bx = blockIdx.x * 32, by = blockIdx.y * 32;
    int x = threadIdx.x, y = threadIdx.y;   // block (32, 8)
    #pragma unroll
    for (int i = 0; i < 32; i += 8)
        t[y + i][x] = src[(size_t)(by + y + i) * EDIM + bx + x];
    __syncthreads();
    #pragma unroll
    for (int i = 0; i < 32; i += 8) {
        float v = t[x][y + i];
        __nv_bfloat16 hb, lb;
        bsplit1(v, hb, lb);
        size_t o = base + (size_t)(bx + y + i) * EDIM + by + x;
        dstHi[o] = hb;
        dstLo[o] = lb;
    }
}

// ---------------------------------------------------------------------------
// Convert fp32 array to bf16 hi/lo planes (pairwise)
// ---------------------------------------------------------------------------
__global__ void __launch_bounds__(256) cvt_planes_kernel(
    const float2* __restrict__ src, uint32_t* __restrict__ hi,
    uint32_t* __restrict__ lo, int npairs)
{
    int i = blockIdx.x * 256 + threadIdx.x;
    if (i >= npairs) return;
    float2 v = src[i];
    uint32_t h, l;
    bsplit2(v.x, v.y, h, l);
    hi[i] = h;
    lo[i] = l;
}

// ---------------------------------------------------------------------------
// bf16x3 GEMM, 3-stage cp.async pipeline, interleaved hi|lo smem rows.
// Row layout: [hi 16 words][lo 16 words][pad 4] -> stride 36 (conflict-free).
// Stage = A 128 rows + B 128 rows = 256*36 words = 36864 B; 3 stages.
// ---------------------------------------------------------------------------
#define GSTRIDE 36
#define STAGE_W (256 * GSTRIDE)               // words per stage
#define GEMM_SMEM_BYTES (3 * STAGE_W * 4)     // 110592 B

__device__ __forceinline__ void gemm_stage_bf16(
    uint32_t* s,
    const uint32_t* __restrict__ Ah, const uint32_t* __restrict__ Al,
    const uint32_t* __restrict__ Bh, const uint32_t* __restrict__ Bl,
    int M, int bm, int bn, int koffw, int tid)
{
    #pragma unroll
    for (int r = 0; r < 8; r++) {
        int slot = tid + 256 * r;          // 0..2047
        int isB  = slot >> 10;
        int c    = slot & 1023;
        int row  = c >> 3;
        int ch   = c & 7;
        int half = ch >> 2;                // 0 = hi, 1 = lo
        int wo   = (ch & 3) * 4;
        int grow = isB ? (bn + row) : (bm + row);
        bool v = isB || (grow < M);
        size_t ga = (size_t)(v ? grow : 0) * 512 + koffw + wo;
        const uint32_t* src = isB ? (half ? Bl : Bh) : (half ? Al : Ah);
        uint32_t* sd = s + (isB ? 128 * GSTRIDE : 0)
                     + row * GSTRIDE + half * 16 + wo;
        cpa16(sd, &src[ga], v);
    }
    CP_COMMIT();
}

__device__ __forceinline__ void gemm_tile(
    const uint32_t* __restrict__ Ah, const uint32_t* __restrict__ Al,
    const uint32_t* __restrict__ Bh, const uint32_t* __restrict__ Bl,
    const float* __restrict__ bias, float* __restrict__ Cf,
    uint32_t* __restrict__ Ch, uint32_t* __restrict__ Cl,
    __nv_bfloat16* __restrict__ VtH, __nv_bfloat16* __restrict__ VtL,
    int M, int hasBias, int bm, int bn)
{
    extern __shared__ uint32_t gsm[];

    const int tid  = threadIdx.x;
    const int wid  = tid >> 5;
    const int lane = tid & 31;
    const int wm = wid & 1;
    const int wn = wid >> 1;
    const int g = lane >> 2;
    const int t = lane & 3;
    // ldmatrix per-lane offset (stride GSTRIDE, conflict-free: 36 % 8 == 4)
    const uint32_t lz = (((lane & 15) * GSTRIDE) + ((lane >> 4) << 2)) * 4;
    const uint32_t smem0 = (uint32_t)__cvta_generic_to_shared(gsm);

    gemm_stage_bf16(gsm,           Ah, Al, Bh, Bl, M, bm, bn, 0,  tid);
    gemm_stage_bf16(gsm + STAGE_W, Ah, Al, Bh, Bl, M, bm, bn, 16, tid);

    float acc[4][4][4];
    #pragma unroll
    for (int mi = 0; mi < 4; mi++)
        #pragma unroll
        for (int ni = 0; ni < 4; ni++)
            #pragma unroll
            for (int q = 0; q < 4; q++) acc[mi][ni][q] = 0.f;

    #pragma unroll 1
    for (int kt = 0; kt < 32; kt++) {
        if (kt + 1 < 32) CP_WAIT1(); else CP_WAIT0();
        __syncthreads();
        if (kt + 2 < 32)   // stage into buffer last read at kt-1 (safe: barrier)
            gemm_stage_bf16(gsm + ((kt + 2) % 3) * STAGE_W, Ah, Al, Bh, Bl,
                            M, bm, bn, (kt + 2) * 16, tid);

        const uint32_t sb = smem0 + ((uint32_t)(kt % 3) * STAGE_W) * 4 + lz;
        const uint32_t bbase = sb + (uint32_t)(128 * GSTRIDE) * 4;

        #pragma unroll
        for (int ks = 0; ks < 2; ks++) {
            const uint32_t kbB = (uint32_t)ks * 32;   // 8 words
            uint32_t ah[4][4], al[4][4], bh[2][4], bl[2][4];
            #pragma unroll
            for (int mi = 0; mi < 4; mi++) {
                uint32_t ro = (uint32_t)((wm * 64 + mi * 16) * GSTRIDE) * 4 + kbB;
                ldm_x4(ah[mi], sb + ro);
                ldm_x4(al[mi], sb + ro + 64);   // lo half at +16 words
            }
            #pragma unroll
            for (int p = 0; p < 2; p++) {
                uint32_t ro = (uint32_t)((wn * 32 + p * 16) * GSTRIDE) * 4 + kbB;
                ldm_x4(bh[p], bbase + ro);
                ldm_x4(bl[p], bbase + ro + 64);
            }
            #pragma unroll
            for (int ni = 0; ni < 4; ni++) {
                int p = ni >> 1, o = ni & 1;
                uint32_t bh0 = bh[p][o], bh1 = bh[p][o + 2];
                uint32_t bl0 = bl[p][o], bl1 = bl[p][o + 2];
                #pragma unroll
                for (int mi = 0; mi < 4; mi++)
                    mma_bf16_x3(acc[mi][ni], ah[mi], al[mi], bh0, bh1, bl0, bl1);
            }
        }
    }

    #pragma unroll
    for (int mi = 0; mi < 4; mi++) {
        int row0 = bm + wm * 64 + mi * 16 + g;
        #pragma unroll
        for (int ni = 0; ni < 4; ni++) {
            int col = bn + wn * 32 + ni * 8 + t * 2;
            if (Cf) {
                float b0 = hasBias ? bias[col] : 0.f;
                float b1 = hasBias ? bias[col + 1] : 0.f;
                if (row0 < M) {
                    Cf[(size_t)row0 * EDIM + col]     = acc[mi][ni][0] + b0;
                    Cf[(size_t)row0 * EDIM + col + 1] = acc[mi][ni][1] + b1;
                }
                if (row0 + 8 < M) {
                    Cf[(size_t)(row0 + 8) * EDIM + col]     = acc[mi][ni][2] + b0;
                    Cf[(size_t)(row0 + 8) * EDIM + col + 1] = acc[mi][ni][3] + b1;
                }
            } else if (Ch) {
                uint32_t h, l;
                if (row0 < M) {
                    bsplit2(acc[mi][ni][0], acc[mi][ni][1], h, l);
                    size_t w = (size_t)row0 * 512 + (col >> 1);
                    Ch[w] = h; Cl[w] = l;
                }
                if (row0 + 8 < M) {
                    bsplit2(acc[mi][ni][2], acc[mi][ni][3], h, l);
                    size_t w = (size_t)(row0 + 8) * 512 + (col >> 1);
                    Ch[w] = h; Cl[w] = l;
                }
            } else {
                // transposed V planes: dst[(b*16+h)*64+s][j]
                int bb = row0 >> 10, j = row0 & (TLEN - 1);
                size_t r0a = ((size_t)(bb * HEADS + (col >> 6)) * 64
                              + (col & 63)) * TLEN;
                size_t r1a = r0a + TLEN;   // col+1 -> s+1 (col is even)
                __nv_bfloat16 hh, ll;
                bsplit1(acc[mi][ni][0], hh, ll);
                VtH[r0a + j] = hh;     VtL[r0a + j] = ll;
                bsplit1(acc[mi][ni][2], hh, ll);
                VtH[r0a + j + 8] = hh; VtL[r0a + j + 8] = ll;
                bsplit1(acc[mi][ni][1], hh, ll);
                VtH[r1a + j] = hh;     VtL[r1a + j] = ll;
                bsplit1(acc[mi][ni][3], hh, ll);
                VtH[r1a + j + 8] = hh; VtL[r1a + j + 8] = ll;
            }
        }
    }
}

// Fused projections, compact grid (8, 112): y<96 -> z=y>>5 (Q/K/V, 32 blocks
// each), y>=96 -> z=3 (KP, 16 blocks). No dead CTAs.
__global__ void __launch_bounds__(256, 2) fused_gemm_kernel(
    const uint32_t* __restrict__ Xh, const uint32_t* __restrict__ Xl,
    const uint32_t* __restrict__ Ph, const uint32_t* __restrict__ Pl,
    const uint32_t* __restrict__ Wh, const uint32_t* __restrict__ Wl,
    uint32_t* __restrict__ Qh, uint32_t* __restrict__ Ql,
    uint32_t* __restrict__ Kh, uint32_t* __restrict__ Kl,
    __nv_bfloat16* __restrict__ Vth, __nv_bfloat16* __restrict__ Vtl,
    uint32_t* __restrict__ KPh, uint32_t* __restrict__ KPl)
{
    const int yy = blockIdx.y;
    const int z  = (yy < 96) ? (yy >> 5) : 3;
    const int ym = (yy < 96) ? (yy & 31) : (yy - 96);
    const uint32_t* Ah = (z < 3) ? Xh : Ph;
    const uint32_t* Al = (z < 3) ? Xl : Pl;
    const int M = (z < 3) ? (BATCH * TLEN) : P2;
    const int bm = ym * 128;
    const uint32_t* Bh = Wh + (size_t)z * EDIM * EDIM / 2;
    const uint32_t* Bl = Wl + (size_t)z * EDIM * EDIM / 2;
    uint32_t* Ch = (z == 0) ? Qh : (z == 1) ? Kh : (z == 3) ? KPh : nullptr;
    uint32_t* Cl = (z == 0) ? Ql : (z == 1) ? Kl : (z == 3) ? KPl : nullptr;
    __nv_bfloat16* VtH = (z == 2) ? Vth : nullptr;
    __nv_bfloat16* VtL = (z == 2) ? Vtl : nullptr;
    gemm_tile(Ah, Al, Bh, Bl, nullptr, nullptr, Ch, Cl, VtH, VtL,
              M, 0, bm, blockIdx.x * 128);
}

__global__ void __launch_bounds__(256, 2) gemmU_kernel(
    const uint32_t* __restrict__ Ah, const uint32_t* __restrict__ Al,
    const uint32_t* __restrict__ Bh, const uint32_t* __restrict__ Bl,
    const float* __restrict__ bias, float* __restrict__ C)
{
    gemm_tile(Ah, Al, Bh, Bl, bias, C, nullptr, nullptr, nullptr, nullptr,
              BATCH * TLEN, 1, blockIdx.y * 128, blockIdx.x * 128);
}

// ---------------------------------------------------------------------------
// Fused dpt + cpp (vectorized uint4 plane loads)
// ---------------------------------------------------------------------------
__global__ void __launch_bounds__(256) dptcpp_kernel(
    const uint32_t* __restrict__ Kh, const uint32_t* __restrict__ Kl,
    const uint32_t* __restrict__ KPh, const uint32_t* __restrict__ KPl,
    const float* __restrict__ parma, const float* __restrict__ parmb,
    float* __restrict__ dpt, float* __restrict__ cpp)
{
    int idx = blockIdx.x * 256 + threadIdx.x;
    const uint32_t *srcH, *srcL;
    const float* par;
    size_t base;
    int h;
    if (idx < BATCH * HEADS * TLEN) {
        int j = idx & (TLEN - 1);
        h = (idx >> 10) & (HEADS - 1);
        int b = idx >> 14;
        base = (size_t)(b * TLEN + j) * 512 + h * 32;
        srcH = Kh; srcL = Kl; par = parma;
    } else {
        int i2 = idx - BATCH * HEADS * TLEN;
        if (i2 >= HEADS * P2) return;
        h = i2 / P2;
        int p = i2 - h * P2;
        base = (size_t)p * 512 + h * 32;
        srcH = KPh; srcL = KPl; par = parmb;
    }
    const uint4* h4 = (const uint4*)(srcH + base);
    const uint4* l4 = (const uint4*)(srcL + base);
    const float4* p4 = (const float4*)(par + h * SDIM);
    float s = 0.f;
    #pragma unroll
    for (int w = 0; w < 8; w++) {
        uint4 hh = h4[w];
        uint4 ll = l4[w];
        float4 pa0 = p4[2 * w], pa1 = p4[2 * w + 1];
        float2 f;
        f = brecon2(hh.x, ll.x); s = fmaf(pa0.x, f.x, fmaf(pa0.y, f.y, s));
        f = brecon2(hh.y, ll.y); s = fmaf(pa0.z, f.x, fmaf(pa0.w, f.y, s));
        f = brecon2(hh.z, ll.z); s = fmaf(pa1.x, f.x, fmaf(pa1.y, f.y, s));
        f = brecon2(hh.w, ll.w); s = fmaf(pa1.z, f.x, fmaf(pa1.w, f.y, s));
    }
    if (idx < BATCH * HEADS * TLEN) dpt[idx] = s;
    else cpp[idx - BATCH * HEADS * TLEN] = s;
}

// ---------------------------------------------------------------------------
// Tensor-core attention: all mma bf16x3 (k16, ldmatrix) on hi/lo planes.
// Scores: Q @ [K;KPband]^T band-masked. PV: P planes @ Vt planes.
// ---------------------------------------------------------------------------
#define QW 36    // word stride for plane rows
#define SP 196   // S matrix stride (floats)

// word offsets
#define OFF_QH 0
#define OFF_QL 2304
#define OFF_BH 4608
#define OFF_BL 11520
#define OFF_VTH 18432
#define OFF_VTL 20736
#define OFF_PH 23040
#define OFF_PL 25344
#define OFF_DP 27648
#define OFF_CP 27712
#define OFF_SC 27840
#define OFF_LS 27904
#define ATTN_SMEM_BYTES (27968 * 4)

__global__ void __launch_bounds__(256, 2) attn_kernel(
    const uint32_t* __restrict__ Qh, const uint32_t* __restrict__ Ql,
    const uint32_t* __restrict__ Kh, const uint32_t* __restrict__ Kl,
    const uint32_t* __restrict__ Vth, const uint32_t* __restrict__ Vtl,
    const uint32_t* __restrict__ KPh, const uint32_t* __restrict__ KPl,
    const float* __restrict__ dpt, const float* __restrict__ cpp,
    uint32_t* __restrict__ Oh, uint32_t* __restrict__ Ol)
{
    extern __shared__ uint32_t smw[];
    uint32_t* Qhs = smw + OFF_QH;       // [64][QW]
    uint32_t* Qls = smw + OFF_QL;
    uint32_t* Bhs = smw + OFF_BH;       // [192][QW]
    uint32_t* Bls = smw + OFF_BL;
    float* Ssm  = (float*)(smw + OFF_BH);   // [64][SP] aliases B planes
    uint32_t* Vths = smw + OFF_VTH;     // [64 s][QW]
    uint32_t* Vtls = smw + OFF_VTL;
    __nv_bfloat16* PH = (__nv_bfloat16*)(smw + OFF_PH);  // [64][72]
    __nv_bfloat16* PL = (__nv_bfloat16*)(smw + OFF_PL);
    float* dpts = (float*)(smw + OFF_DP);
    float* cpps = (float*)(smw + OFF_CP);
    float* scale_sm = (float*)(smw + OFF_SC);
    float* lsum_sm  = (float*)(smw + OFF_LS);

    const int tid  = threadIdx.x;
    const int lane = tid & 31;
    const int wid  = tid >> 5;
    const int g = lane >> 2;
    const int t = lane & 3;
    const int rm = (wid & 1) * 32;      // scores m-base
    const int cn = (wid >> 1) * 48;     // scores n-base
    const int sm0 = (wid & 3) * 16;     // PV m-slice
    const int pn0 = (wid >> 2) * 32;    // PV n-slice
    const int tx = tid & 15, ty = tid >> 4;
    const uint32_t lzq = (((lane & 15) * QW) + ((lane >> 4) << 2)) * 4;
    const uint32_t smb = (uint32_t)__cvta_generic_to_shared(smw);

    const int b = blockIdx.z, h = blockIdx.y;
    const int it = (int)gridDim.x - 1 - (int)blockIdx.x;
    const int I0 = it * 64;
    const int hw = h * 32;

    // Stage Q planes once
    for (int idx = tid; idx < 512; idx += 256) {
        int r = idx >> 3, w = (idx & 7) * 4;
        size_t gq = (size_t)(b * TLEN + I0 + r) * 512 + hw + w;
        cpa16(&Qhs[r * QW + w], &Qh[gq], true);
        cpa16(&Qls[r * QW + w], &Ql[gq], true);
    }
    CP_COMMIT();

    float m_r[4], l_r[4];
    #pragma unroll
    for (int i = 0; i < 4; i++) { m_r[i] = -INFINITY; l_r[i] = 0.f; }
    float o_acc[4][4];
    #pragma unroll
    for (int n = 0; n < 4; n++)
        #pragma unroll
        for (int q = 0; q < 4; q++) o_acc[n][q] = 0.f;

    for (int jt = 0; jt <= it; jt++) {
        const int J0 = jt * 64;
        const int pbase = I0 + J0;
        const int d = I0 - J0;

        __syncthreads();

        // ---- Stage K planes, KP planes, Vt planes ----
        for (int idx = tid; idx < 512; idx += 256) {
            int c = idx >> 3, w = (idx & 7) * 4;
            size_t gk = (size_t)(b * TLEN + J0 + c) * 512 + hw + w;
            cpa16(&Bhs[c * QW + w], &Kh[gk], true);
            cpa16(&Bls[c * QW + w], &Kl[gk], true);
        }
        for (int idx = tid; idx < 1024; idx += 256) {
            int pl = idx >> 3, w = (idx & 7) * 4;
            int p = pbase + pl;
            bool v = p < P2;
            size_t gp = (size_t)(v ? p : 0) * 512 + hw + w;
            cpa16(&Bhs[(64 + pl) * QW + w], &KPh[gp], v);
            cpa16(&Bls[(64 + pl) * QW + w], &KPl[gp], v);
        }
        for (int idx = tid; idx < 512; idx += 256) {
            int s = idx >> 3, w = (idx & 7) * 4;
            size_t gv = ((size_t)((b * HEADS + h) * 64 + s)) * 512
                      + (J0 >> 1) + w;
            cpa16(&Vths[s * QW + w], &Vth[gv], true);
            cpa16(&Vtls[s * QW + w], &Vtl[gv], true);
        }
        CP_COMMIT();
        if (tid < 64) dpts[tid] = dpt[((size_t)(b * HEADS + h)) * TLEN + J0 + tid];
        if (tid < 128) {
            int p = pbase + tid;
            cpps[tid] = (p < P2) ? cpp[(size_t)h * P2 + p] : 0.f;
        }
        CP_WAIT0();
        __syncthreads();

        // Fragment need-masks (warp-uniform)
        bool need[2][6];
        #pragma unroll
        for (int mi = 0; mi < 2; mi++) {
            int m0 = rm + 16 * mi;
            int cmax = m0 + 15 + d; if (cmax > 63) cmax = 63;
            #pragma unroll
            for (int nt = 0; nt < 6; nt++) {
                int n0 = cn + nt * 8;
                if (n0 < 64) {
                    need[mi][nt] = (n0 <= m0 + 15 + d);
                } else {
                    int pl0 = n0 - 64;
                    need[mi][nt] = (pl0 + 7 >= m0) && (pl0 <= m0 + 15 + cmax);
                }
            }
        }

        // ---- Scores mma: bf16x3 m16n8k16 via ldmatrix ----
        float sacc[2][6][4];
        #pragma unroll
        for (int mi = 0; mi < 2; mi++)
            #pragma unroll
            for (int n = 0; n < 6; n++)
                #pragma unroll
                for (int q = 0; q < 4; q++) sacc[mi][n][q] = 0.f;

        const uint32_t qh0 = smb + OFF_QH * 4 + lzq;
        const uint32_t ql0 = smb + OFF_QL * 4 + lzq;
        const uint32_t bh0b = smb + OFF_BH * 4 + lzq;
        const uint32_t bl0b = smb + OFF_BL * 4 + lzq;

        #pragma unroll
        for (int kc = 0; kc < 4; kc++) {
            const uint32_t kbB = (uint32_t)(kc * 8) * 4;
            uint32_t ah[2][4], al[2][4], bh[3][4], bl[3][4];
            #pragma unroll
            for (int mi = 0; mi < 2; mi++) {
                uint32_t ro = (uint32_t)((rm + 16 * mi) * QW) * 4 + kbB;
                ldm_x4(ah[mi], qh0 + ro);
                ldm_x4(al[mi], ql0 + ro);
            }
            #pragma unroll
            for (int p = 0; p < 3; p++) {
                uint32_t ro = (uint32_t)((cn + p * 16) * QW) * 4 + kbB;
                ldm_x4(bh[p], bh0b + ro);
                ldm_x4(bl[p], bl0b + ro);
            }
            #pragma unroll
            for (int nt = 0; nt < 6; nt++) {
                if (!need[0][nt] && !need[1][nt]) continue;
                int p = nt >> 1, o = nt & 1;
                uint32_t b0 = bh[p][o], b1 = bh[p][o + 2];
                uint32_t c0 = bl[p][o], c1 = bl[p][o + 2];
                if (need[0][nt])
                    mma_bf16_x3(sacc[0][nt], ah[0], al[0], b0, b1, c0, c1);
                if (need[1][nt])
                    mma_bf16_x3(sacc[1][nt], ah[1], al[1], b0, b1, c0, c1);
            }
        }

        __syncthreads();   // done reading B planes; overwrite as Ssm
        #pragma unroll
        for (int mi = 0; mi < 2; mi++) {
            int r0 = rm + 16 * mi + g;
            #pragma unroll
            for (int nt = 0; nt < 6; nt++) {
                if (!need[mi][nt]) continue;
                int n0 = cn + nt * 8 + 2 * t;
                Ssm[r0 * SP + n0]           = sacc[mi][nt][0];
                Ssm[r0 * SP + n0 + 1]       = sacc[mi][nt][1];
                Ssm[(r0 + 8) * SP + n0]     = sacc[mi][nt][2];
                Ssm[(r0 + 8) * SP + n0 + 1] = sacc[mi][nt][3];
            }
        }
        __syncthreads();

        // ---- Softmax (fp32 SIMT), P written as bf16 hi/lo planes ----
        #pragma unroll
        for (int i = 0; i < 4; i++) {
            int r = ty + 16 * i;
            float sc[4];
            float mx = -INFINITY;
            #pragma unroll
            for (int j = 0; j < 4; j++) {
                int c = tx + 16 * j;
                float v = Ssm[r * SP + c] + Ssm[r * SP + 64 + r + c]
                        + dpts[c] + cpps[r + c];
                if (c > r + d) v = -1e30f;
                sc[j] = v;
                mx = fmaxf(mx, v);
            }
            #pragma unroll
            for (int off = 8; off >= 1; off >>= 1)
                mx = fmaxf(mx, __shfl_xor_sync(0xffffffffu, mx, off));
            float mnew = fmaxf(m_r[i], mx);
            float scale = __expf(m_r[i] - mnew);
            m_r[i] = mnew;
            float rs = 0.f;
            #pragma unroll
            for (int j = 0; j < 4; j++) {
                float p = __expf(sc[j] - mnew);
                int c = tx + 16 * j;
                __nv_bfloat16 hb, lb;
                bsplit1(p, hb, lb);
                PH[r * 72 + c] = hb;
                PL[r * 72 + c] = lb;
                rs += p;
            }
            #pragma unroll
            for (int off = 8; off >= 1; off >>= 1)
                rs += __shfl_xor_sync(0xffffffffu, rs, off);
            l_r[i] = l_r[i] * scale + rs;
            if (tx == 0) {
                scale_sm[r] = scale;
                lsum_sm[r]  = l_r[i];
            }
        }
        __syncthreads();

        // ---- PV mma: O = O*scale + P @ Vt^T (bf16x3, ldmatrix) ----
        const float sA = scale_sm[sm0 + g];
        const float sB = scale_sm[sm0 + g + 8];
        #pragma unroll
        for (int nt = 0; nt < 4; nt++) {
            o_acc[nt][0] *= sA; o_acc[nt][1] *= sA;
            o_acc[nt][2] *= sB; o_acc[nt][3] *= sB;
        }
        const uint32_t ph0 = smb + OFF_PH * 4 + lzq;
        const uint32_t pl0b = smb + OFF_PL * 4 + lzq;
        const uint32_t vh0 = smb + OFF_VTH * 4 + lzq;
        const uint32_t vl0 = smb + OFF_VTL * 4 + lzq;
        #pragma unroll
        for (int kc = 0; kc < 4; kc++) {
            const uint32_t kbB = (uint32_t)(kc * 8) * 4;
            uint32_t ah[4], al[4], bh[2][4], bl[2][4];
            {
                uint32_t ro = (uint32_t)(sm0 * QW) * 4 + kbB;
                ldm_x4(ah, ph0 + ro);
                ldm_x4(al, pl0b + ro);
            }
            #pragma unroll
            for (int p = 0; p < 2; p++) {
                uint32_t ro = (uint32_t)((pn0 + p * 16) * QW) * 4 + kbB;
                ldm_x4(bh[p], vh0 + ro);
                ldm_x4(bl[p], vl0 + ro);
            }
            #pragma unroll
            for (int nt = 0; nt < 4; nt++) {
                int p = nt >> 1, o = nt & 1;
                mma_bf16_x3(o_acc[nt], ah, al,
                            bh[p][o], bh[p][o + 2], bl[p][o], bl[p][o + 2]);
            }
        }
    }

    __syncthreads();
    const float invA = 1.f / lsum_sm[sm0 + g];
    const float invB = 1.f / lsum_sm[sm0 + g + 8];
    const size_t row0 = (size_t)(b * TLEN + I0 + sm0 + g) * EDIM;
    const size_t row1 = row0 + 8 * EDIM;
    #pragma unroll
    for (int nt = 0; nt < 4; nt++) {
        size_t col = (size_t)h * SDIM + pn0 + nt * 8 + 2 * t;   // even
        uint32_t hA, lA, hB, lB;
        bsplit2(o_acc[nt][0] * invA, o_acc[nt][1] * invA, hA, lA);
        bsplit2(o_acc[nt][2] * invB, o_acc[nt][3] * invB, hB, lB);
        Oh[(row0 + col) >> 1] = hA;
        Ol[(row0 + col) >> 1] = lA;
        Oh[(row1 + col) >> 1] = hB;
        Ol[(row1 + col) >> 1] = lB;
    }
}

// ---------------------------------------------------------------------------
// Launch
// ---------------------------------------------------------------------------
extern "C" void kernel_launch(void* const* d_in, const int* in_sizes, int n_in,
                              void* d_out, int out_size)
{
    const float* x     = (const float*)d_in[0];
    const float* Wq    = (const float*)d_in[1];
    const float* Wk    = (const float*)d_in[2];
    const float* Wkp   = (const float*)d_in[3];
    const float* Wv    = (const float*)d_in[4];
    const float* Wu    = (const float*)d_in[5];
    const float* bu    = (const float*)d_in[6];
    const float* parma = (const float*)d_in[7];
    const float* parmb = (const float*)d_in[8];
    const float* pos   = (const float*)d_in[9];
    float* out = (float*)d_out;

    float *dptb, *cppb;
    void *Xh, *Xl, *Ph, *Pl, *Wh, *Wl, *Qh, *Ql, *Kh, *Kl, *KPh, *KPl;
    void *Vth, *Vtl, *ATTh, *ATTl;
    cudaGetSymbolAddress((void**)&dptb, g_dpt);
    cudaGetSymbolAddress((void**)&cppb, g_cpp);
    cudaGetSymbolAddress(&Xh,  g_Xh);
    cudaGetSymbolAddress(&Xl,  g_Xl);
    cudaGetSymbolAddress(&Ph,  g_Psrch);
    cudaGetSymbolAddress(&Pl,  g_Psrcl);
    cudaGetSymbolAddress(&Wh,  g_Wh);
    cudaGetSymbolAddress(&Wl,  g_Wl);
    cudaGetSymbolAddress(&Qh,  g_Qh);
    cudaGetSymbolAddress(&Ql,  g_Ql);
    cudaGetSymbolAddress(&Kh,  g_Kh);
    cudaGetSymbolAddress(&Kl,  g_Kl);
    cudaGetSymbolAddress(&KPh, g_KPh);
    cudaGetSymbolAddress(&KPl, g_KPl);
    cudaGetSymbolAddress(&Vth, g_Vth);
    cudaGetSymbolAddress(&Vtl, g_Vtl);
    cudaGetSymbolAddress(&ATTh, g_ATTh);
    cudaGetSymbolAddress(&ATTl, g_ATTl);

    // 1) transpose + split weights into bf16 planes
    transpose5_kernel<<<dim3(32, 32, 5), dim3(32, 8)>>>(
        Wq, Wk, Wv, Wkp, Wu, (__nv_bfloat16*)Wh, (__nv_bfloat16*)Wl);

    // 2) split x and pos into planes
    const int xpairs = BATCH * TLEN * EDIM / 2;
    const int ppairs = P2 * EDIM / 2;
    cvt_planes_kernel<<<(xpairs + 255) / 256, 256>>>(
        (const float2*)x, (uint32_t*)Xh, (uint32_t*)Xl, xpairs);
    cvt_planes_kernel<<<(ppairs + 255) / 256, 256>>>(
        (const float2*)pos, (uint32_t*)Ph, (uint32_t*)Pl, ppairs);

    // 3) fused projections (compact grid, 3-stage pipeline)
    cudaFuncSetAttribute(fused_gemm_kernel,
                         cudaFuncAttributeMaxDynamicSharedMemorySize,
                         GEMM_SMEM_BYTES);
    fused_gemm_kernel<<<dim3(8, 112), 256, GEMM_SMEM_BYTES>>>(
        (const uint32_t*)Xh, (const uint32_t*)Xl,
        (const uint32_t*)Ph, (const uint32_t*)Pl,
        (const uint32_t*)Wh, (const uint32_t*)Wl,
        (uint32_t*)Qh, (uint32_t*)Ql, (uint32_t*)Kh, (uint32_t*)Kl,
        (__nv_bfloat16*)Vth, (__nv_bfloat16*)Vtl,
        (uint32_t*)KPh, (uint32_t*)KPl);

    // 4) fused dpt + cpp (vectorized)
    const int total_small = BATCH * HEADS * TLEN + HEADS * P2;
    dptcpp_kernel<<<(total_small + 255) / 256, 256>>>(
        (const uint32_t*)Kh, (const uint32_t*)Kl,
        (const uint32_t*)KPh, (const uint32_t*)KPl,
        parma, parmb, dptb, cppb);

    // 5) attention (all-bf16x3; writes ATT planes)
    cudaFuncSetAttribute(attn_kernel,
                         cudaFuncAttributeMaxDynamicSharedMemorySize,
                         ATTN_SMEM_BYTES);
    attn_kernel<<<dim3(TLEN / 64, HEADS, BATCH), 256, ATTN_SMEM_BYTES>>>(
        (const uint32_t*)Qh, (const uint32_t*)Ql,
        (const uint32_t*)Kh, (const uint32_t*)Kl,
        (const uint32_t*)Vth, (const uint32_t*)Vtl,
        (const uint32_t*)KPh, (const uint32_t*)KPl,
        dptb, cppb, (uint32_t*)ATTh, (uint32_t*)ATTl);

    // 6) output projection (+bias, bf16x3)
    cudaFuncSetAttribute(gemmU_kernel,
                         cudaFuncAttributeMaxDynamicSharedMemorySize,
                         GEMM_SMEM_BYTES);
    gemmU_kernel<<<dim3(8, 32), 256, GEMM_SMEM_BYTES>>>(
        (const uint32_t*)ATTh, (const uint32_t*)ATTl,
        (const uint32_t*)Wh + 4 * (size_t)EDIM * EDIM / 2,
        (const uint32_t*)Wl + 4 * (size_t)EDIM * EDIM / 2,
        bu, out);
}

// round 16
// speedup vs baseline: 1.0433x; 1.0235x over previous
#include <cuda_runtime.h>
#include <cuda_bf16.h>
#include <math.h>
#include <stdint.h>

// Problem constants
#define BATCH 4
#define TLEN  1024
#define EDIM  1024
#define HEADS 16
#define SDIM  64
#define P2    2047   // 2*t - 1

// ---------------------------------------------------------------------------
// Scratch (device globals — no runtime allocation allowed)
// ---------------------------------------------------------------------------
__device__ float g_dpt[(size_t)BATCH * HEADS * TLEN];
__device__ float g_cpp[(size_t)HEADS * P2];
// bf16 hi/lo planes
__device__ __nv_bfloat16 g_Xh [(size_t)BATCH * TLEN * EDIM];
__device__ __nv_bfloat16 g_Xl [(size_t)BATCH * TLEN * EDIM];
__device__ __nv_bfloat16 g_Psrch[(size_t)P2 * EDIM];
__device__ __nv_bfloat16 g_Psrcl[(size_t)P2 * EDIM];
__device__ __nv_bfloat16 g_Wh [(size_t)5 * EDIM * EDIM];  // transposed [N,K]
__device__ __nv_bfloat16 g_Wl [(size_t)5 * EDIM * EDIM];
__device__ __nv_bfloat16 g_Qh [(size_t)BATCH * TLEN * EDIM];
__device__ __nv_bfloat16 g_Ql [(size_t)BATCH * TLEN * EDIM];
__device__ __nv_bfloat16 g_Kh [(size_t)BATCH * TLEN * EDIM];
__device__ __nv_bfloat16 g_Kl [(size_t)BATCH * TLEN * EDIM];
__device__ __nv_bfloat16 g_KPh[(size_t)P2 * EDIM];
__device__ __nv_bfloat16 g_KPl[(size_t)P2 * EDIM];
// V stored TRANSPOSED as planes: [b][h][s][j]
__device__ __nv_bfloat16 g_Vth[(size_t)BATCH * HEADS * SDIM * TLEN];
__device__ __nv_bfloat16 g_Vtl[(size_t)BATCH * HEADS * SDIM * TLEN];
__device__ __nv_bfloat16 g_ATTh[(size_t)BATCH * TLEN * EDIM];
__device__ __nv_bfloat16 g_ATTl[(size_t)BATCH * TLEN * EDIM];

// ---------------------------------------------------------------------------
// helpers
// ---------------------------------------------------------------------------
__device__ __forceinline__ void mma_bf16(float* c,
    uint32_t a0, uint32_t a1, uint32_t a2, uint32_t a3,
    uint32_t b0, uint32_t b1)
{
    asm volatile(
        "mma.sync.aligned.m16n8k16.row.col.f32.bf16.bf16.f32 "
        "{%0,%1,%2,%3}, {%4,%5,%6,%7}, {%8,%9}, {%0,%1,%2,%3};"
        : "+f"(c[0]), "+f"(c[1]), "+f"(c[2]), "+f"(c[3])
        : "r"(a0), "r"(a1), "r"(a2), "r"(a3), "r"(b0), "r"(b1));
}
__device__ __forceinline__ void mma_bf16_x3(float* c,
    const uint32_t* ah, const uint32_t* al,
    uint32_t bh0, uint32_t bh1, uint32_t bl0, uint32_t bl1)
{
    mma_bf16(c, al[0], al[1], al[2], al[3], bh0, bh1);
    mma_bf16(c, ah[0], ah[1], ah[2], ah[3], bl0, bl1);
    mma_bf16(c, ah[0], ah[1], ah[2], ah[3], bh0, bh1);
}
__device__ __forceinline__ void ldm_x4(uint32_t* r, uint32_t saddr) {
    asm volatile(
        "ldmatrix.sync.aligned.m8n8.x4.shared.b16 {%0,%1,%2,%3}, [%4];"
        : "=r"(r[0]), "=r"(r[1]), "=r"(r[2]), "=r"(r[3]) : "r"(saddr));
}
__device__ __forceinline__ void bsplit2(float v0, float v1,
                                        uint32_t& hi, uint32_t& lo)
{
    __nv_bfloat162 h = __float22bfloat162_rn(make_float2(v0, v1));
    float r0 = v0 - __bfloat162float(h.x);
    float r1 = v1 - __bfloat162float(h.y);
    __nv_bfloat162 l = __float22bfloat162_rn(make_float2(r0, r1));
    hi = *(uint32_t*)&h;
    lo = *(uint32_t*)&l;
}
__device__ __forceinline__ void bsplit1(float v, __nv_bfloat16& h,
                                        __nv_bfloat16& l)
{
    h = __float2bfloat16_rn(v);
    l = __float2bfloat16_rn(v - __bfloat162float(h));
}
__device__ __forceinline__ float2 brecon2(uint32_t h, uint32_t l) {
    __nv_bfloat162 hb = *(__nv_bfloat162*)&h;
    __nv_bfloat162 lb = *(__nv_bfloat162*)&l;
    return make_float2(__bfloat162float(hb.x) + __bfloat162float(lb.x),
                       __bfloat162float(hb.y) + __bfloat162float(lb.y));
}

// cp.async helpers (baseline PTX, sm_80+); v=false -> zero-fill 16B
__device__ __forceinline__ void cpa16(void* smem_dst, const void* gsrc, bool v) {
    uint32_t s = (uint32_t)__cvta_generic_to_shared(smem_dst);
    int sz = v ? 16 : 0;
    asm volatile("cp.async.cg.shared.global [%0], [%1], 16, %2;"
                 :: "r"(s), "l"(gsrc), "r"(sz) : "memory");
}
#define CP_COMMIT() asm volatile("cp.async.commit_group;" ::: "memory")
#define CP_WAIT1()  asm volatile("cp.async.wait_group 1;" ::: "memory")
#define CP_WAIT0()  asm volatile("cp.async.wait_group 0;" ::: "memory")

// ---------------------------------------------------------------------------
// Transpose 5 weights into bf16 hi/lo planes
// ---------------------------------------------------------------------------
__global__ void __launch_bounds__(256) transpose5_kernel(
    const float* __restrict__ W0, const float* __restrict__ W1,
    const float* __restrict__ W2, const float* __restrict__ W3,
    const float* __restrict__ W4,
    __nv_bfloat16* __restrict__ dstHi, __nv_bfloat16* __restrict__ dstLo)
{
    __shared__ float t[32][33];
    int z = blockIdx.z;
    const float* src = (z == 0) ? W0 : (z == 1) ? W1 : (z == 2) ? W2
                     : (z == 3) ? W3 : W4;
    size_t base = (size_t)z * EDIM * EDIM;
    int bx = blockIdx.x * 32, by = blockIdx.y * 32;
    int x = threadIdx.x, y = threadIdx.y;   // block (32, 8)
    #pragma unroll
    for (int i = 0; i < 32; i += 8)
        t[y + i][x] = src[(size_t)(by + y + i) * EDIM + bx + x];
    __syncthreads();
    #pragma unroll
    for (int i = 0; i < 32; i += 8) {
        float v = t[x][y + i];
        __nv_bfloat16 hb, lb;
        bsplit1(v, hb, lb);
        size_t o = base + (size_t)(bx + y + i) * EDIM + by + x;
        dstHi[o] = hb;
        dstLo[o] = lb;
    }
}

// ---------------------------------------------------------------------------
// Convert fp32 array to bf16 hi/lo planes (pairwise)
// ---------------------------------------------------------------------------
__global__ void __launch_bounds__(256) cvt_planes_kernel(
    const float2* __restrict__ src, uint32_t* __restrict__ hi,
    uint32_t* __restrict__ lo, int npairs)
{
    int i = blockIdx.x * 256 + threadIdx.x;
    if (i >= npairs) return;
    float2 v = src[i];
    uint32_t h, l;
    bsplit2(v.x, v.y, h, l);
    hi[i] = h;
    lo[i] = l;
}

// ---------------------------------------------------------------------------
// bf16x3 tensor-core GEMM tile with ldmatrix fragment loads.
// 2-stage cp.async pipeline, separate hi/lo planes (proven 264-267us config).
// ---------------------------------------------------------------------------
#define GPW 20                         // uint32 words per smem plane row
#define PLANE_W (128 * GPW)            // 2560 words per plane
#define GEMM_SMEM_BYTES (8 * PLANE_W * 4)   // 81920 B

__device__ __forceinline__ void gemm_stage_bf16(
    uint32_t* s,
    const uint32_t* __restrict__ Ah, const uint32_t* __restrict__ Al,
    const uint32_t* __restrict__ Bh, const uint32_t* __restrict__ Bl,
    int M, int bm, int bn, int koffw, int tid)
{
    #pragma unroll
    for (int r = 0; r < 2; r++) {
        int slot = tid + 256 * r;          // 0..511
        int row = slot >> 2, ch = (slot & 3) * 4;
        int grow = bm + row;
        bool v = grow < M;
        size_t ga = (size_t)(v ? grow : 0) * 512 + koffw + ch;
        size_t gb = (size_t)(bn + row) * 512 + koffw + ch;
        uint32_t* sd = s + row * GPW + ch;
        cpa16(sd,               &Ah[ga], v);
        cpa16(sd + PLANE_W,     &Al[ga], v);
        cpa16(sd + 2 * PLANE_W, &Bh[gb], true);
        cpa16(sd + 3 * PLANE_W, &Bl[gb], true);
    }
    CP_COMMIT();
}

__device__ __forceinline__ void gemm_tile(
    const uint32_t* __restrict__ Ah, const uint32_t* __restrict__ Al,
    const uint32_t* __restrict__ Bh, const uint32_t* __restrict__ Bl,
    const float* __restrict__ bias, float* __restrict__ Cf,
    uint32_t* __restrict__ Ch, uint32_t* __restrict__ Cl,
    __nv_bfloat16* __restrict__ VtH, __nv_bfloat16* __restrict__ VtL,
    int M, int hasBias, int bm, int bn)
{
    extern __shared__ uint32_t gsm[];
    uint32_t* buf0 = gsm;
    uint32_t* buf1 = gsm + 4 * PLANE_W;

    const int tid  = threadIdx.x;
    const int wid  = tid >> 5;
    const int lane = tid & 31;
    const int wm = wid & 1;
    const int wn = wid >> 1;
    const int g = lane >> 2;
    const int t = lane & 3;
    const uint32_t lz = (((lane & 15) * GPW) + ((lane >> 4) << 2)) * 4;
    const uint32_t smem0 = (uint32_t)__cvta_generic_to_shared(gsm);

    gemm_stage_bf16(buf0, Ah, Al, Bh, Bl, M, bm, bn, 0,  tid);
    gemm_stage_bf16(buf1, Ah, Al, Bh, Bl, M, bm, bn, 16, tid);

    float acc[4][4][4];
    #pragma unroll
    for (int mi = 0; mi < 4; mi++)
        #pragma unroll
        for (int ni = 0; ni < 4; ni++)
            #pragma unroll
            for (int q = 0; q < 4; q++) acc[mi][ni][q] = 0.f;

    #pragma unroll 1
    for (int kt = 0; kt < 32; kt++) {
        if (kt + 1 < 32) CP_WAIT1(); else CP_WAIT0();
        __syncthreads();
        const uint32_t bufo = (kt & 1) ? (4 * PLANE_W * 4) : 0;
        const uint32_t aho = smem0 + bufo + lz;
        const uint32_t alo = aho + PLANE_W * 4;
        const uint32_t bho = alo + PLANE_W * 4;
        const uint32_t blo = bho + PLANE_W * 4;

        #pragma unroll
        for (int ks = 0; ks < 2; ks++) {
            const uint32_t kbB = (uint32_t)(ks * 8) * 4;
            uint32_t ah[4][4], al[4][4], bh[2][4], bl[2][4];
            #pragma unroll
            for (int mi = 0; mi < 4; mi++) {
                uint32_t ro = (uint32_t)((wm * 64 + mi * 16) * GPW) * 4 + kbB;
                ldm_x4(ah[mi], aho + ro);
                ldm_x4(al[mi], alo + ro);
            }
            #pragma unroll
            for (int p = 0; p < 2; p++) {
                uint32_t ro = (uint32_t)((wn * 32 + p * 16) * GPW) * 4 + kbB;
                ldm_x4(bh[p], bho + ro);
                ldm_x4(bl[p], blo + ro);
            }
            #pragma unroll
            for (int ni = 0; ni < 4; ni++) {
                int p = ni >> 1, o = ni & 1;
                uint32_t bh0 = bh[p][o], bh1 = bh[p][o + 2];
                uint32_t bl0 = bl[p][o], bl1 = bl[p][o + 2];
                #pragma unroll
                for (int mi = 0; mi < 4; mi++)
                    mma_bf16_x3(acc[mi][ni], ah[mi], al[mi], bh0, bh1, bl0, bl1);
            }
        }
        __syncthreads();
        if (kt + 2 < 32)
            gemm_stage_bf16((kt & 1) ? buf1 : buf0, Ah, Al, Bh, Bl,
                            M, bm, bn, (kt + 2) * 16, tid);
    }

    #pragma unroll
    for (int mi = 0; mi < 4; mi++) {
        int row0 = bm + wm * 64 + mi * 16 + g;
        #pragma unroll
        for (int ni = 0; ni < 4; ni++) {
            int col = bn + wn * 32 + ni * 8 + t * 2;
            if (Cf) {
                float b0 = hasBias ? bias[col] : 0.f;
                float b1 = hasBias ? bias[col + 1] : 0.f;
                if (row0 < M) {
                    Cf[(size_t)row0 * EDIM + col]     = acc[mi][ni][0] + b0;
                    Cf[(size_t)row0 * EDIM + col + 1] = acc[mi][ni][1] + b1;
                }
                if (row0 + 8 < M) {
                    Cf[(size_t)(row0 + 8) * EDIM + col]     = acc[mi][ni][2] + b0;
                    Cf[(size_t)(row0 + 8) * EDIM + col + 1] = acc[mi][ni][3] + b1;
                }
            } else if (Ch) {
                uint32_t h, l;
                if (row0 < M) {
                    bsplit2(acc[mi][ni][0], acc[mi][ni][1], h, l);
                    size_t w = (size_t)row0 * 512 + (col >> 1);
                    Ch[w] = h; Cl[w] = l;
                }
                if (row0 + 8 < M) {
                    bsplit2(acc[mi][ni][2], acc[mi][ni][3], h, l);
                    size_t w = (size_t)(row0 + 8) * 512 + (col >> 1);
                    Ch[w] = h; Cl[w] = l;
                }
            } else {
                // transposed V planes: dst[(b*16+h)*64+s][j]
                int bb = row0 >> 10, j = row0 & (TLEN - 1);
                size_t r0a = ((size_t)(bb * HEADS + (col >> 6)) * 64
                              + (col & 63)) * TLEN;
                size_t r1a = r0a + TLEN;   // col+1 -> s+1 (col is even)
                __nv_bfloat16 hh, ll;
                bsplit1(acc[mi][ni][0], hh, ll);
                VtH[r0a + j] = hh;     VtL[r0a + j] = ll;
                bsplit1(acc[mi][ni][2], hh, ll);
                VtH[r0a + j + 8] = hh; VtL[r0a + j + 8] = ll;
                bsplit1(acc[mi][ni][1], hh, ll);
                VtH[r1a + j] = hh;     VtL[r1a + j] = ll;
                bsplit1(acc[mi][ni][3], hh, ll);
                VtH[r1a + j + 8] = hh; VtL[r1a + j + 8] = ll;
            }
        }
    }
}

// Fused projections, compact grid (8, 112): y<96 -> z=y>>5 (Q/K/V), y>=96 -> KP.
__global__ void __launch_bounds__(256, 2) fused_gemm_kernel(
    const uint32_t* __restrict__ Xh, const uint32_t* __restrict__ Xl,
    const uint32_t* __restrict__ Ph, const uint32_t* __restrict__ Pl,
    const uint32_t* __restrict__ Wh, const uint32_t* __restrict__ Wl,
    uint32_t* __restrict__ Qh, uint32_t* __restrict__ Ql,
    uint32_t* __restrict__ Kh, uint32_t* __restrict__ Kl,
    __nv_bfloat16* __restrict__ Vth, __nv_bfloat16* __restrict__ Vtl,
    uint32_t* __restrict__ KPh, uint32_t* __restrict__ KPl)
{
    const int yy = blockIdx.y;
    const int z  = (yy < 96) ? (yy >> 5) : 3;
    const int ym = (yy < 96) ? (yy & 31) : (yy - 96);
    const uint32_t* Ah = (z < 3) ? Xh : Ph;
    const uint32_t* Al = (z < 3) ? Xl : Pl;
    const int M = (z < 3) ? (BATCH * TLEN) : P2;
    const int bm = ym * 128;
    const uint32_t* Bh = Wh + (size_t)z * EDIM * EDIM / 2;
    const uint32_t* Bl = Wl + (size_t)z * EDIM * EDIM / 2;
    uint32_t* Ch = (z == 0) ? Qh : (z == 1) ? Kh : (z == 3) ? KPh : nullptr;
    uint32_t* Cl = (z == 0) ? Ql : (z == 1) ? Kl : (z == 3) ? KPl : nullptr;
    __nv_bfloat16* VtH = (z == 2) ? Vth : nullptr;
    __nv_bfloat16* VtL = (z == 2) ? Vtl : nullptr;
    gemm_tile(Ah, Al, Bh, Bl, nullptr, nullptr, Ch, Cl, VtH, VtL,
              M, 0, bm, blockIdx.x * 128);
}

__global__ void __launch_bounds__(256, 2) gemmU_kernel(
    const uint32_t* __restrict__ Ah, const uint32_t* __restrict__ Al,
    const uint32_t* __restrict__ Bh, const uint32_t* __restrict__ Bl,
    const float* __restrict__ bias, float* __restrict__ C)
{
    gemm_tile(Ah, Al, Bh, Bl, bias, C, nullptr, nullptr, nullptr, nullptr,
              BATCH * TLEN, 1, blockIdx.y * 128, blockIdx.x * 128);
}

// ---------------------------------------------------------------------------
// Fused dpt + cpp (vectorized uint4 plane loads)
// ---------------------------------------------------------------------------
__global__ void __launch_bounds__(256) dptcpp_kernel(
    const uint32_t* __restrict__ Kh, const uint32_t* __restrict__ Kl,
    const uint32_t* __restrict__ KPh, const uint32_t* __restrict__ KPl,
    const float* __restrict__ parma, const float* __restrict__ parmb,
    float* __restrict__ dpt, float* __restrict__ cpp)
{
    int idx = blockIdx.x * 256 + threadIdx.x;
    const uint32_t *srcH, *srcL;
    const float* par;
    size_t base;
    int h;
    if (idx < BATCH * HEADS * TLEN) {
        int j = idx & (TLEN - 1);
        h = (idx >> 10) & (HEADS - 1);
        int b = idx >> 14;
        base = (size_t)(b * TLEN + j) * 512 + h * 32;
        srcH = Kh; srcL = Kl; par = parma;
    } else {
        int i2 = idx - BATCH * HEADS * TLEN;
        if (i2 >= HEADS * P2) return;
        h = i2 / P2;
        int p = i2 - h * P2;
        base = (size_t)p * 512 + h * 32;
        srcH = KPh; srcL = KPl; par = parmb;
    }
    const uint4* h4 = (const uint4*)(srcH + base);
    const uint4* l4 = (const uint4*)(srcL + base);
    const float4* p4 = (const float4*)(par + h * SDIM);
    float s = 0.f;
    #pragma unroll
    for (int w = 0; w < 8; w++) {
        uint4 hh = h4[w];
        uint4 ll = l4[w];
        float4 pa0 = p4[2 * w], pa1 = p4[2 * w + 1];
        float2 f;
        f = brecon2(hh.x, ll.x); s = fmaf(pa0.x, f.x, fmaf(pa0.y, f.y, s));
        f = brecon2(hh.y, ll.y); s = fmaf(pa0.z, f.x, fmaf(pa0.w, f.y, s));
        f = brecon2(hh.z, ll.z); s = fmaf(pa1.x, f.x, fmaf(pa1.y, f.y, s));
        f = brecon2(hh.w, ll.w); s = fmaf(pa1.z, f.x, fmaf(pa1.w, f.y, s));
    }
    if (idx < BATCH * HEADS * TLEN) dpt[idx] = s;
    else cpp[idx - BATCH * HEADS * TLEN] = s;
}

// ---------------------------------------------------------------------------
// Tensor-core attention: all mma bf16x3 (k16, ldmatrix) on hi/lo planes.
// Softmax uses contiguous per-thread columns (c = 4*tx + j) for vector LDS/STS.
// ---------------------------------------------------------------------------
#define QW 36    // word stride for plane rows
#define SP 196   // S matrix stride (floats)

// word offsets
#define OFF_QH 0
#define OFF_QL 2304
#define OFF_BH 4608
#define OFF_BL 11520
#define OFF_VTH 18432
#define OFF_VTL 20736
#define OFF_PH 23040
#define OFF_PL 25344
#define OFF_DP 27648
#define OFF_CP 27712
#define OFF_SC 27840
#define OFF_LS 27904
#define ATTN_SMEM_BYTES (27968 * 4)

__global__ void __launch_bounds__(256, 2) attn_kernel(
    const uint32_t* __restrict__ Qh, const uint32_t* __restrict__ Ql,
    const uint32_t* __restrict__ Kh, const uint32_t* __restrict__ Kl,
    const uint32_t* __restrict__ Vth, const uint32_t* __restrict__ Vtl,
    const uint32_t* __restrict__ KPh, const uint32_t* __restrict__ KPl,
    const float* __restrict__ dpt, const float* __restrict__ cpp,
    uint32_t* __restrict__ Oh, uint32_t* __restrict__ Ol)
{
    extern __shared__ uint32_t smw[];
    uint32_t* Qhs = smw + OFF_QH;       // [64][QW]
    uint32_t* Qls = smw + OFF_QL;
    uint32_t* Bhs = smw + OFF_BH;       // [192][QW]
    uint32_t* Bls = smw + OFF_BL;
    float* Ssm  = (float*)(smw + OFF_BH);   // [64][SP] aliases B planes
    uint32_t* Vths = smw + OFF_VTH;     // [64 s][QW]
    uint32_t* Vtls = smw + OFF_VTL;
    __nv_bfloat16* PH = (__nv_bfloat16*)(smw + OFF_PH);  // [64][72]
    __nv_bfloat16* PL = (__nv_bfloat16*)(smw + OFF_PL);
    float* dpts = (float*)(smw + OFF_DP);
    float* cpps = (float*)(smw + OFF_CP);
    float* scale_sm = (float*)(smw + OFF_SC);
    float* lsum_sm  = (float*)(smw + OFF_LS);

    const int tid  = threadIdx.x;
    const int lane = tid & 31;
    const int wid  = tid >> 5;
    const int g = lane >> 2;
    const int t = lane & 3;
    const int rm = (wid & 1) * 32;      // scores m-base
    const int cn = (wid >> 1) * 48;     // scores n-base
    const int sm0 = (wid & 3) * 16;     // PV m-slice
    const int pn0 = (wid >> 2) * 32;    // PV n-slice
    const int tx = tid & 15, ty = tid >> 4;
    const uint32_t lzq = (((lane & 15) * QW) + ((lane >> 4) << 2)) * 4;
    const uint32_t smb = (uint32_t)__cvta_generic_to_shared(smw);

    const int b = blockIdx.z, h = blockIdx.y;
    const int it = (int)gridDim.x - 1 - (int)blockIdx.x;
    const int I0 = it * 64;
    const int hw = h * 32;

    // Stage Q planes once
    for (int idx = tid; idx < 512; idx += 256) {
        int r = idx >> 3, w = (idx & 7) * 4;
        size_t gq = (size_t)(b * TLEN + I0 + r) * 512 + hw + w;
        cpa16(&Qhs[r * QW + w], &Qh[gq], true);
        cpa16(&Qls[r * QW + w], &Ql[gq], true);
    }
    CP_COMMIT();

    float m_r[4], l_r[4];
    #pragma unroll
    for (int i = 0; i < 4; i++) { m_r[i] = -INFINITY; l_r[i] = 0.f; }
    float o_acc[4][4];
    #pragma unroll
    for (int n = 0; n < 4; n++)
        #pragma unroll
        for (int q = 0; q < 4; q++) o_acc[n][q] = 0.f;

    for (int jt = 0; jt <= it; jt++) {
        const int J0 = jt * 64;
        const int pbase = I0 + J0;
        const int d = I0 - J0;

        __syncthreads();

        // ---- Stage K planes, KP planes, Vt planes ----
        for (int idx = tid; idx < 512; idx += 256) {
            int c = idx >> 3, w = (idx & 7) * 4;
            size_t gk = (size_t)(b * TLEN + J0 + c) * 512 + hw + w;
            cpa16(&Bhs[c * QW + w], &Kh[gk], true);
            cpa16(&Bls[c * QW + w], &Kl[gk], true);
        }
        for (int idx = tid; idx < 1024; idx += 256) {
            int pl = idx >> 3, w = (idx & 7) * 4;
            int p = pbase + pl;
            bool v = p < P2;
            size_t gp = (size_t)(v ? p : 0) * 512 + hw + w;
            cpa16(&Bhs[(64 + pl) * QW + w], &KPh[gp], v);
            cpa16(&Bls[(64 + pl) * QW + w], &KPl[gp], v);
        }
        for (int idx = tid; idx < 512; idx += 256) {
            int s = idx >> 3, w = (idx & 7) * 4;
            size_t gv = ((size_t)((b * HEADS + h) * 64 + s)) * 512
                      + (J0 >> 1) + w;
            cpa16(&Vths[s * QW + w], &Vth[gv], true);
            cpa16(&Vtls[s * QW + w], &Vtl[gv], true);
        }
        CP_COMMIT();
        if (tid < 64) dpts[tid] = dpt[((size_t)(b * HEADS + h)) * TLEN + J0 + tid];
        if (tid < 128) {
            int p = pbase + tid;
            cpps[tid] = (p < P2) ? cpp[(size_t)h * P2 + p] : 0.f;
        }
        CP_WAIT0();
        __syncthreads();

        // Fragment need-masks (warp-uniform)
        bool need[2][6];
        #pragma unroll
        for (int mi = 0; mi < 2; mi++) {
            int m0 = rm + 16 * mi;
            int cmax = m0 + 15 + d; if (cmax > 63) cmax = 63;
            #pragma unroll
            for (int nt = 0; nt < 6; nt++) {
                int n0 = cn + nt * 8;
                if (n0 < 64) {
                    need[mi][nt] = (n0 <= m0 + 15 + d);
                } else {
                    int pl0 = n0 - 64;
                    need[mi][nt] = (pl0 + 7 >= m0) && (pl0 <= m0 + 15 + cmax);
                }
            }
        }

        // ---- Scores mma: bf16x3 m16n8k16 via ldmatrix ----
        float sacc[2][6][4];
        #pragma unroll
        for (int mi = 0; mi < 2; mi++)
            #pragma unroll
            for (int n = 0; n < 6; n++)
                #pragma unroll
                for (int q = 0; q < 4; q++) sacc[mi][n][q] = 0.f;

        const uint32_t qh0 = smb + OFF_QH * 4 + lzq;
        const uint32_t ql0 = smb + OFF_QL * 4 + lzq;
        const uint32_t bh0b = smb + OFF_BH * 4 + lzq;
        const uint32_t bl0b = smb + OFF_BL * 4 + lzq;

        #pragma unroll
        for (int kc = 0; kc < 4; kc++) {
            const uint32_t kbB = (uint32_t)(kc * 8) * 4;
            uint32_t ah[2][4], al[2][4], bh[3][4], bl[3][4];
            #pragma unroll
            for (int mi = 0; mi < 2; mi++) {
                uint32_t ro = (uint32_t)((rm + 16 * mi) * QW) * 4 + kbB;
                ldm_x4(ah[mi], qh0 + ro);
                ldm_x4(al[mi], ql0 + ro);
            }
            #pragma unroll
            for (int p = 0; p < 3; p++) {
                uint32_t ro = (uint32_t)((cn + p * 16) * QW) * 4 + kbB;
                ldm_x4(bh[p], bh0b + ro);
                ldm_x4(bl[p], bl0b + ro);
            }
            #pragma unroll
            for (int nt = 0; nt < 6; nt++) {
                if (!need[0][nt] && !need[1][nt]) continue;
                int p = nt >> 1, o = nt & 1;
                uint32_t b0 = bh[p][o], b1 = bh[p][o + 2];
                uint32_t c0 = bl[p][o], c1 = bl[p][o + 2];
                if (need[0][nt])
                    mma_bf16_x3(sacc[0][nt], ah[0], al[0], b0, b1, c0, c1);
                if (need[1][nt])
                    mma_bf16_x3(sacc[1][nt], ah[1], al[1], b0, b1, c0, c1);
            }
        }

        __syncthreads();   // done reading B planes; overwrite as Ssm
        #pragma unroll
        for (int mi = 0; mi < 2; mi++) {
            int r0 = rm + 16 * mi + g;
            #pragma unroll
            for (int nt = 0; nt < 6; nt++) {
                if (!need[mi][nt]) continue;
                int n0 = cn + nt * 8 + 2 * t;
                Ssm[r0 * SP + n0]           = sacc[mi][nt][0];
                Ssm[r0 * SP + n0 + 1]       = sacc[mi][nt][1];
                Ssm[(r0 + 8) * SP + n0]     = sacc[mi][nt][2];
                Ssm[(r0 + 8) * SP + n0 + 1] = sacc[mi][nt][3];
            }
        }
        __syncthreads();

        // ---- Softmax (fp32 SIMT), contiguous columns c = 4*tx + j ----
        const float4 dp4 = *(const float4*)&dpts[4 * tx];
        #pragma unroll
        for (int i = 0; i < 4; i++) {
            int r = ty + 16 * i;
            float4 sk = *(const float4*)&Ssm[r * SP + 4 * tx];
            const float* erow = &Ssm[r * SP + 64 + r + 4 * tx];
            const float* crow = &cpps[r + 4 * tx];
            float sc[4];
            sc[0] = sk.x + erow[0] + dp4.x + crow[0];
            sc[1] = sk.y + erow[1] + dp4.y + crow[1];
            sc[2] = sk.z + erow[2] + dp4.z + crow[2];
            sc[3] = sk.w + erow[3] + dp4.w + crow[3];
            float mx = -INFINITY;
            #pragma unroll
            for (int j = 0; j < 4; j++) {
                int c = 4 * tx + j;
                if (c > r + d) sc[j] = -1e30f;
                mx = fmaxf(mx, sc[j]);
            }
            #pragma unroll
            for (int off = 8; off >= 1; off >>= 1)
                mx = fmaxf(mx, __shfl_xor_sync(0xffffffffu, mx, off));
            float mnew = fmaxf(m_r[i], mx);
            float scale = __expf(m_r[i] - mnew);
            m_r[i] = mnew;
            float p0 = __expf(sc[0] - mnew);
            float p1 = __expf(sc[1] - mnew);
            float p2 = __expf(sc[2] - mnew);
            float p3 = __expf(sc[3] - mnew);
            float rs = (p0 + p1) + (p2 + p3);
            uint32_t h01, l01, h23, l23;
            bsplit2(p0, p1, h01, l01);
            bsplit2(p2, p3, h23, l23);
            *(uint2*)&PH[r * 72 + 4 * tx] = make_uint2(h01, h23);
            *(uint2*)&PL[r * 72 + 4 * tx] = make_uint2(l01, l23);
            #pragma unroll
            for (int off = 8; off >= 1; off >>= 1)
                rs += __shfl_xor_sync(0xffffffffu, rs, off);
            l_r[i] = l_r[i] * scale + rs;
            if (tx == 0) {
                scale_sm[r] = scale;
                lsum_sm[r]  = l_r[i];
            }
        }
        __syncthreads();

        // ---- PV mma: O = O*scale + P @ Vt^T (bf16x3, ldmatrix) ----
        const float sA = scale_sm[sm0 + g];
        const float sB = scale_sm[sm0 + g + 8];
        #pragma unroll
        for (int nt = 0; nt < 4; nt++) {
            o_acc[nt][0] *= sA; o_acc[nt][1] *= sA;
            o_acc[nt][2] *= sB; o_acc[nt][3] *= sB;
        }
        const uint32_t ph0 = smb + OFF_PH * 4 + lzq;
        const uint32_t pl0b = smb + OFF_PL * 4 + lzq;
        const uint32_t vh0 = smb + OFF_VTH * 4 + lzq;
        const uint32_t vl0 = smb + OFF_VTL * 4 + lzq;
        #pragma unroll
        for (int kc = 0; kc < 4; kc++) {
            const uint32_t kbB = (uint32_t)(kc * 8) * 4;
            uint32_t ah[4], al[4], bh[2][4], bl[2][4];
            {
                uint32_t ro = (uint32_t)(sm0 * QW) * 4 + kbB;
                ldm_x4(ah, ph0 + ro);
                ldm_x4(al, pl0b + ro);
            }
            #pragma unroll
            for (int p = 0; p < 2; p++) {
                uint32_t ro = (uint32_t)((pn0 + p * 16) * QW) * 4 + kbB;
                ldm_x4(bh[p], vh0 + ro);
                ldm_x4(bl[p], vl0 + ro);
            }
            #pragma unroll
            for (int nt = 0; nt < 4; nt++) {
                int p = nt >> 1, o = nt & 1;
                mma_bf16_x3(o_acc[nt], ah, al,
                            bh[p][o], bh[p][o + 2], bl[p][o], bl[p][o + 2]);
            }
        }
    }

    __syncthreads();
    const float invA = 1.f / lsum_sm[sm0 + g];
    const float invB = 1.f / lsum_sm[sm0 + g + 8];
    const size_t row0 = (size_t)(b * TLEN + I0 + sm0 + g) * EDIM;
    const size_t row1 = row0 + 8 * EDIM;
    #pragma unroll
    for (int nt = 0; nt < 4; nt++) {
        size_t col = (size_t)h * SDIM + pn0 + nt * 8 + 2 * t;   // even
        uint32_t hA, lA, hB, lB;
        bsplit2(o_acc[nt][0] * invA, o_acc[nt][1] * invA, hA, lA);
        bsplit2(o_acc[nt][2] * invB, o_acc[nt][3] * invB, hB, lB);
        Oh[(row0 + col) >> 1] = hA;
        Ol[(row0 + col) >> 1] = lA;
        Oh[(row1 + col) >> 1] = hB;
        Ol[(row1 + col) >> 1] = lB;
    }
}

// ---------------------------------------------------------------------------
// Launch
// ---------------------------------------------------------------------------
extern "C" void kernel_launch(void* const* d_in, const int* in_sizes, int n_in,
                              void* d_out, int out_size)
{
    const float* x     = (const float*)d_in[0];
    const float* Wq    = (const float*)d_in[1];
    const float* Wk    = (const float*)d_in[2];
    const float* Wkp   = (const float*)d_in[3];
    const float* Wv    = (const float*)d_in[4];
    const float* Wu    = (const float*)d_in[5];
    const float* bu    = (const float*)d_in[6];
    const float* parma = (const float*)d_in[7];
    const float* parmb = (const float*)d_in[8];
    const float* pos   = (const float*)d_in[9];
    float* out = (float*)d_out;

    float *dptb, *cppb;
    void *Xh, *Xl, *Ph, *Pl, *Wh, *Wl, *Qh, *Ql, *Kh, *Kl, *KPh, *KPl;
    void *Vth, *Vtl, *ATTh, *ATTl;
    cudaGetSymbolAddress((void**)&dptb, g_dpt);
    cudaGetSymbolAddress((void**)&cppb, g_cpp);
    cudaGetSymbolAddress(&Xh,  g_Xh);
    cudaGetSymbolAddress(&Xl,  g_Xl);
    cudaGetSymbolAddress(&Ph,  g_Psrch);
    cudaGetSymbolAddress(&Pl,  g_Psrcl);
    cudaGetSymbolAddress(&Wh,  g_Wh);
    cudaGetSymbolAddress(&Wl,  g_Wl);
    cudaGetSymbolAddress(&Qh,  g_Qh);
    cudaGetSymbolAddress(&Ql,  g_Ql);
    cudaGetSymbolAddress(&Kh,  g_Kh);
    cudaGetSymbolAddress(&Kl,  g_Kl);
    cudaGetSymbolAddress(&KPh, g_KPh);
    cudaGetSymbolAddress(&KPl, g_KPl);
    cudaGetSymbolAddress(&Vth, g_Vth);
    cudaGetSymbolAddress(&Vtl, g_Vtl);
    cudaGetSymbolAddress(&ATTh, g_ATTh);
    cudaGetSymbolAddress(&ATTl, g_ATTl);

    // 1) transpose + split weights into bf16 planes
    transpose5_kernel<<<dim3(32, 32, 5), dim3(32, 8)>>>(
        Wq, Wk, Wv, Wkp, Wu, (__nv_bfloat16*)Wh, (__nv_bfloat16*)Wl);

    // 2) split x and pos into planes
    const int xpairs = BATCH * TLEN * EDIM / 2;
    const int ppairs = P2 * EDIM / 2;
    cvt_planes_kernel<<<(xpairs + 255) / 256, 256>>>(
        (const float2*)x, (uint32_t*)Xh, (uint32_t*)Xl, xpairs);
    cvt_planes_kernel<<<(ppairs + 255) / 256, 256>>>(
        (const float2*)pos, (uint32_t*)Ph, (uint32_t*)Pl, ppairs);

    // 3) fused projections (compact grid, 2-stage pipeline)
    cudaFuncSetAttribute(fused_gemm_kernel,
                         cudaFuncAttributeMaxDynamicSharedMemorySize,
                         GEMM_SMEM_BYTES);
    fused_gemm_kernel<<<dim3(8, 112), 256, GEMM_SMEM_BYTES>>>(
        (const uint32_t*)Xh, (const uint32_t*)Xl,
        (const uint32_t*)Ph, (const uint32_t*)Pl,
        (const uint32_t*)Wh, (const uint32_t*)Wl,
        (uint32_t*)Qh, (uint32_t*)Ql, (uint32_t*)Kh, (uint32_t*)Kl,
        (__nv_bfloat16*)Vth, (__nv_bfloat16*)Vtl,
        (uint32_t*)KPh, (uint32_t*)KPl);

    // 4) fused dpt + cpp (vectorized)
    const int total_small = BATCH * HEADS * TLEN + HEADS * P2;
    dptcpp_kernel<<<(total_small + 255) / 256, 256>>>(
        (const uint32_t*)Kh, (const uint32_t*)Kl,
        (const uint32_t*)KPh, (const uint32_t*)KPl,
        parma, parmb, dptb, cppb);

    // 5) attention (all-bf16x3; writes ATT planes)
    cudaFuncSetAttribute(attn_kernel,
                         cudaFuncAttributeMaxDynamicSharedMemorySize,
                         ATTN_SMEM_BYTES);
    attn_kernel<<<dim3(TLEN / 64, HEADS, BATCH), 256, ATTN_SMEM_BYTES>>>(
        (const uint32_t*)Qh, (const uint32_t*)Ql,
        (const uint32_t*)Kh, (const uint32_t*)Kl,
        (const uint32_t*)Vth, (const uint32_t*)Vtl,
        (const uint32_t*)KPh, (const uint32_t*)KPl,
        dptb, cppb, (uint32_t*)ATTh, (uint32_t*)ATTl);

    // 6) output projection (+bias, bf16x3)
    cudaFuncSetAttribute(gemmU_kernel,
                         cudaFuncAttributeMaxDynamicSharedMemorySize,
                         GEMM_SMEM_BYTES);
    gemmU_kernel<<<dim3(8, 32), 256, GEMM_SMEM_BYTES>>>(
        (const uint32_t*)ATTh, (const uint32_t*)ATTl,
        (const uint32_t*)Wh + 4 * (size_t)EDIM * EDIM / 2,
        (const uint32_t*)Wl + 4 * (size_t)EDIM * EDIM / 2,
        bu, out);
}

// round 17
// speedup vs baseline: 1.0467x; 1.0033x over previous
#include <cuda_runtime.h>
#include <cuda_bf16.h>
#include <math.h>
#include <stdint.h>

// Problem constants
#define BATCH 4
#define TLEN  1024
#define EDIM  1024
#define HEADS 16
#define SDIM  64
#define P2    2047   // 2*t - 1

// ---------------------------------------------------------------------------
// Scratch (device globals — no runtime allocation allowed)
// ---------------------------------------------------------------------------
__device__ __nv_bfloat16 g_Xh [(size_t)BATCH * TLEN * EDIM];
__device__ __nv_bfloat16 g_Xl [(size_t)BATCH * TLEN * EDIM];
__device__ __nv_bfloat16 g_Psrch[(size_t)P2 * EDIM];
__device__ __nv_bfloat16 g_Psrcl[(size_t)P2 * EDIM];
__device__ __nv_bfloat16 g_Wh [(size_t)5 * EDIM * EDIM];  // transposed [N,K]
__device__ __nv_bfloat16 g_Wl [(size_t)5 * EDIM * EDIM];
__device__ __nv_bfloat16 g_Qh [(size_t)BATCH * TLEN * EDIM];
__device__ __nv_bfloat16 g_Ql [(size_t)BATCH * TLEN * EDIM];
__device__ __nv_bfloat16 g_Kh [(size_t)BATCH * TLEN * EDIM];
__device__ __nv_bfloat16 g_Kl [(size_t)BATCH * TLEN * EDIM];
__device__ __nv_bfloat16 g_KPh[(size_t)P2 * EDIM];
__device__ __nv_bfloat16 g_KPl[(size_t)P2 * EDIM];
// V stored TRANSPOSED as planes: [b][h][s][j]
__device__ __nv_bfloat16 g_Vth[(size_t)BATCH * HEADS * SDIM * TLEN];
__device__ __nv_bfloat16 g_Vtl[(size_t)BATCH * HEADS * SDIM * TLEN];
__device__ __nv_bfloat16 g_ATTh[(size_t)BATCH * TLEN * EDIM];
__device__ __nv_bfloat16 g_ATTl[(size_t)BATCH * TLEN * EDIM];

// ---------------------------------------------------------------------------
// helpers
// ---------------------------------------------------------------------------
__device__ __forceinline__ void mma_bf16(float* c,
    uint32_t a0, uint32_t a1, uint32_t a2, uint32_t a3,
    uint32_t b0, uint32_t b1)
{
    asm volatile(
        "mma.sync.aligned.m16n8k16.row.col.f32.bf16.bf16.f32 "
        "{%0,%1,%2,%3}, {%4,%5,%6,%7}, {%8,%9}, {%0,%1,%2,%3};"
        : "+f"(c[0]), "+f"(c[1]), "+f"(c[2]), "+f"(c[3])
        : "r"(a0), "r"(a1), "r"(a2), "r"(a3), "r"(b0), "r"(b1));
}
__device__ __forceinline__ void mma_bf16_x3(float* c,
    const uint32_t* ah, const uint32_t* al,
    uint32_t bh0, uint32_t bh1, uint32_t bl0, uint32_t bl1)
{
    mma_bf16(c, al[0], al[1], al[2], al[3], bh0, bh1);
    mma_bf16(c, ah[0], ah[1], ah[2], ah[3], bl0, bl1);
    mma_bf16(c, ah[0], ah[1], ah[2], ah[3], bh0, bh1);
}
__device__ __forceinline__ void ldm_x4(uint32_t* r, uint32_t saddr) {
    asm volatile(
        "ldmatrix.sync.aligned.m8n8.x4.shared.b16 {%0,%1,%2,%3}, [%4];"
        : "=r"(r[0]), "=r"(r[1]), "=r"(r[2]), "=r"(r[3]) : "r"(saddr));
}
__device__ __forceinline__ void bsplit2(float v0, float v1,
                                        uint32_t& hi, uint32_t& lo)
{
    __nv_bfloat162 h = __float22bfloat162_rn(make_float2(v0, v1));
    float r0 = v0 - __bfloat162float(h.x);
    float r1 = v1 - __bfloat162float(h.y);
    __nv_bfloat162 l = __float22bfloat162_rn(make_float2(r0, r1));
    hi = *(uint32_t*)&h;
    lo = *(uint32_t*)&l;
}
__device__ __forceinline__ void bsplit1(float v, __nv_bfloat16& h,
                                        __nv_bfloat16& l)
{
    h = __float2bfloat16_rn(v);
    l = __float2bfloat16_rn(v - __bfloat162float(h));
}
__device__ __forceinline__ float2 brecon2(uint32_t h, uint32_t l) {
    __nv_bfloat162 hb = *(__nv_bfloat162*)&h;
    __nv_bfloat162 lb = *(__nv_bfloat162*)&l;
    return make_float2(__bfloat162float(hb.x) + __bfloat162float(lb.x),
                       __bfloat162float(hb.y) + __bfloat162float(lb.y));
}

// cp.async helpers (baseline PTX, sm_80+); v=false -> zero-fill 16B
__device__ __forceinline__ void cpa16(void* smem_dst, const void* gsrc, bool v) {
    uint32_t s = (uint32_t)__cvta_generic_to_shared(smem_dst);
    int sz = v ? 16 : 0;
    asm volatile("cp.async.cg.shared.global [%0], [%1], 16, %2;"
                 :: "r"(s), "l"(gsrc), "r"(sz) : "memory");
}
#define CP_COMMIT() asm volatile("cp.async.commit_group;" ::: "memory")
#define CP_WAIT1()  asm volatile("cp.async.wait_group 1;" ::: "memory")
#define CP_WAIT0()  asm volatile("cp.async.wait_group 0;" ::: "memory")

// ---------------------------------------------------------------------------
// Transpose 5 weights into bf16 hi/lo planes
// ---------------------------------------------------------------------------
__global__ void __launch_bounds__(256) transpose5_kernel(
    const float* __restrict__ W0, const float* __restrict__ W1,
    const float* __restrict__ W2, const float* __restrict__ W3,
    const float* __restrict__ W4,
    __nv_bfloat16* __restrict__ dstHi, __nv_bfloat16* __restrict__ dstLo)
{
    __shared__ float t[32][33];
    int z = blockIdx.z;
    const float* src = (z == 0) ? W0 : (z == 1) ? W1 : (z == 2) ? W2
                     : (z == 3) ? W3 : W4;
    size_t base = (size_t)z * EDIM * EDIM;
    int bx = blockIdx.x * 32, by = blockIdx.y * 32;
    int x = threadIdx.x, y = threadIdx.y;   // block (32, 8)
    #pragma unroll
    for (int i = 0; i < 32; i += 8)
        t[y + i][x] = src[(size_t)(by + y + i) * EDIM + bx + x];
    __syncthreads();
    #pragma unroll
    for (int i = 0; i < 32; i += 8) {
        float v = t[x][y + i];
        __nv_bfloat16 hb, lb;
        bsplit1(v, hb, lb);
        size_t o = base + (size_t)(bx + y + i) * EDIM + by + x;
        dstHi[o] = hb;
        dstLo[o] = lb;
    }
}

// ---------------------------------------------------------------------------
// Convert fp32 array to bf16 hi/lo planes (pairwise)
// ---------------------------------------------------------------------------
__global__ void __launch_bounds__(256) cvt_planes_kernel(
    const float2* __restrict__ src, uint32_t* __restrict__ hi,
    uint32_t* __restrict__ lo, int npairs)
{
    int i = blockIdx.x * 256 + threadIdx.x;
    if (i >= npairs) return;
    float2 v = src[i];
    uint32_t h, l;
    bsplit2(v.x, v.y, h, l);
    hi[i] = h;
    lo[i] = l;
}

// ---------------------------------------------------------------------------
// bf16x3 tensor-core GEMM tile with ldmatrix fragment loads.
// 2-stage cp.async pipeline, separate hi/lo planes.
// ---------------------------------------------------------------------------
#define GPW 20                         // uint32 words per smem plane row
#define PLANE_W (128 * GPW)            // 2560 words per plane
#define GEMM_SMEM_BYTES (8 * PLANE_W * 4)   // 81920 B

__device__ __forceinline__ void gemm_stage_bf16(
    uint32_t* s,
    const uint32_t* __restrict__ Ah, const uint32_t* __restrict__ Al,
    const uint32_t* __restrict__ Bh, const uint32_t* __restrict__ Bl,
    int M, int bm, int bn, int koffw, int tid)
{
    #pragma unroll
    for (int r = 0; r < 2; r++) {
        int slot = tid + 256 * r;          // 0..511
        int row = slot >> 2, ch = (slot & 3) * 4;
        int grow = bm + row;
        bool v = grow < M;
        size_t ga = (size_t)(v ? grow : 0) * 512 + koffw + ch;
        size_t gb = (size_t)(bn + row) * 512 + koffw + ch;
        uint32_t* sd = s + row * GPW + ch;
        cpa16(sd,               &Ah[ga], v);
        cpa16(sd + PLANE_W,     &Al[ga], v);
        cpa16(sd + 2 * PLANE_W, &Bh[gb], true);
        cpa16(sd + 3 * PLANE_W, &Bl[gb], true);
    }
    CP_COMMIT();
}

__device__ __forceinline__ void gemm_tile(
    const uint32_t* __restrict__ Ah, const uint32_t* __restrict__ Al,
    const uint32_t* __restrict__ Bh, const uint32_t* __restrict__ Bl,
    const float* __restrict__ bias, float* __restrict__ Cf,
    uint32_t* __restrict__ Ch, uint32_t* __restrict__ Cl,
    __nv_bfloat16* __restrict__ VtH, __nv_bfloat16* __restrict__ VtL,
    int M, int hasBias, int bm, int bn)
{
    extern __shared__ uint32_t gsm[];
    uint32_t* buf0 = gsm;
    uint32_t* buf1 = gsm + 4 * PLANE_W;

    const int tid  = threadIdx.x;
    const int wid  = tid >> 5;
    const int lane = tid & 31;
    const int wm = wid & 1;
    const int wn = wid >> 1;
    const int g = lane >> 2;
    const int t = lane & 3;
    const uint32_t lz = (((lane & 15) * GPW) + ((lane >> 4) << 2)) * 4;
    const uint32_t smem0 = (uint32_t)__cvta_generic_to_shared(gsm);

    gemm_stage_bf16(buf0, Ah, Al, Bh, Bl, M, bm, bn, 0,  tid);
    gemm_stage_bf16(buf1, Ah, Al, Bh, Bl, M, bm, bn, 16, tid);

    float acc[4][4][4];
    #pragma unroll
    for (int mi = 0; mi < 4; mi++)
        #pragma unroll
        for (int ni = 0; ni < 4; ni++)
            #pragma unroll
            for (int q = 0; q < 4; q++) acc[mi][ni][q] = 0.f;

    #pragma unroll 1
    for (int kt = 0; kt < 32; kt++) {
        if (kt + 1 < 32) CP_WAIT1(); else CP_WAIT0();
        __syncthreads();
        const uint32_t bufo = (kt & 1) ? (4 * PLANE_W * 4) : 0;
        const uint32_t aho = smem0 + bufo + lz;
        const uint32_t alo = aho + PLANE_W * 4;
        const uint32_t bho = alo + PLANE_W * 4;
        const uint32_t blo = bho + PLANE_W * 4;

        #pragma unroll
        for (int ks = 0; ks < 2; ks++) {
            const uint32_t kbB = (uint32_t)(ks * 8) * 4;
            uint32_t ah[4][4], al[4][4], bh[2][4], bl[2][4];
            #pragma unroll
            for (int mi = 0; mi < 4; mi++) {
                uint32_t ro = (uint32_t)((wm * 64 + mi * 16) * GPW) * 4 + kbB;
                ldm_x4(ah[mi], aho + ro);
                ldm_x4(al[mi], alo + ro);
            }
            #pragma unroll
            for (int p = 0; p < 2; p++) {
                uint32_t ro = (uint32_t)((wn * 32 + p * 16) * GPW) * 4 + kbB;
                ldm_x4(bh[p], bho + ro);
                ldm_x4(bl[p], blo + ro);
            }
            #pragma unroll
            for (int ni = 0; ni < 4; ni++) {
                int p = ni >> 1, o = ni & 1;
                uint32_t bh0 = bh[p][o], bh1 = bh[p][o + 2];
                uint32_t bl0 = bl[p][o], bl1 = bl[p][o + 2];
                #pragma unroll
                for (int mi = 0; mi < 4; mi++)
                    mma_bf16_x3(acc[mi][ni], ah[mi], al[mi], bh0, bh1, bl0, bl1);
            }
        }
        __syncthreads();
        if (kt + 2 < 32)
            gemm_stage_bf16((kt & 1) ? buf1 : buf0, Ah, Al, Bh, Bl,
                            M, bm, bn, (kt + 2) * 16, tid);
    }

    #pragma unroll
    for (int mi = 0; mi < 4; mi++) {
        int row0 = bm + wm * 64 + mi * 16 + g;
        #pragma unroll
        for (int ni = 0; ni < 4; ni++) {
            int col = bn + wn * 32 + ni * 8 + t * 2;
            if (Cf) {
                float b0 = hasBias ? bias[col] : 0.f;
                float b1 = hasBias ? bias[col + 1] : 0.f;
                if (row0 < M) {
                    Cf[(size_t)row0 * EDIM + col]     = acc[mi][ni][0] + b0;
                    Cf[(size_t)row0 * EDIM + col + 1] = acc[mi][ni][1] + b1;
                }
                if (row0 + 8 < M) {
                    Cf[(size_t)(row0 + 8) * EDIM + col]     = acc[mi][ni][2] + b0;
                    Cf[(size_t)(row0 + 8) * EDIM + col + 1] = acc[mi][ni][3] + b1;
                }
            } else if (Ch) {
                uint32_t h, l;
                if (row0 < M) {
                    bsplit2(acc[mi][ni][0], acc[mi][ni][1], h, l);
                    size_t w = (size_t)row0 * 512 + (col >> 1);
                    Ch[w] = h; Cl[w] = l;
                }
                if (row0 + 8 < M) {
                    bsplit2(acc[mi][ni][2], acc[mi][ni][3], h, l);
                    size_t w = (size_t)(row0 + 8) * 512 + (col >> 1);
                    Ch[w] = h; Cl[w] = l;
                }
            } else {
                // transposed V planes: dst[(b*16+h)*64+s][j]
                int bb = row0 >> 10, j = row0 & (TLEN - 1);
                size_t r0a = ((size_t)(bb * HEADS + (col >> 6)) * 64
                              + (col & 63)) * TLEN;
                size_t r1a = r0a + TLEN;   // col+1 -> s+1 (col is even)
                __nv_bfloat16 hh, ll;
                bsplit1(acc[mi][ni][0], hh, ll);
                VtH[r0a + j] = hh;     VtL[r0a + j] = ll;
                bsplit1(acc[mi][ni][2], hh, ll);
                VtH[r0a + j + 8] = hh; VtL[r0a + j + 8] = ll;
                bsplit1(acc[mi][ni][1], hh, ll);
                VtH[r1a + j] = hh;     VtL[r1a + j] = ll;
                bsplit1(acc[mi][ni][3], hh, ll);
                VtH[r1a + j + 8] = hh; VtL[r1a + j + 8] = ll;
            }
        }
    }
}

// Fused projections: z=0 Q planes, z=1 K planes, z=2 V^T planes, z=3 KP planes.
// (Padded z-grid: measured faster than compact y-dispatch.)
__global__ void __launch_bounds__(256, 2) fused_gemm_kernel(
    const uint32_t* __restrict__ Xh, const uint32_t* __restrict__ Xl,
    const uint32_t* __restrict__ Ph, const uint32_t* __restrict__ Pl,
    const uint32_t* __restrict__ Wh, const uint32_t* __restrict__ Wl,
    uint32_t* __restrict__ Qh, uint32_t* __restrict__ Ql,
    uint32_t* __restrict__ Kh, uint32_t* __restrict__ Kl,
    __nv_bfloat16* __restrict__ Vth, __nv_bfloat16* __restrict__ Vtl,
    uint32_t* __restrict__ KPh, uint32_t* __restrict__ KPl)
{
    const int z = blockIdx.z;
    const uint32_t* Ah = (z < 3) ? Xh : Ph;
    const uint32_t* Al = (z < 3) ? Xl : Pl;
    const int M = (z < 3) ? (BATCH * TLEN) : P2;
    const int bm = blockIdx.y * 128;
    if (bm >= M) return;
    const uint32_t* Bh = Wh + (size_t)z * EDIM * EDIM / 2;
    const uint32_t* Bl = Wl + (size_t)z * EDIM * EDIM / 2;
    uint32_t* Ch = (z == 0) ? Qh : (z == 1) ? Kh : (z == 3) ? KPh : nullptr;
    uint32_t* Cl = (z == 0) ? Ql : (z == 1) ? Kl : (z == 3) ? KPl : nullptr;
    __nv_bfloat16* VtH = (z == 2) ? Vth : nullptr;
    __nv_bfloat16* VtL = (z == 2) ? Vtl : nullptr;
    gemm_tile(Ah, Al, Bh, Bl, nullptr, nullptr, Ch, Cl, VtH, VtL,
              M, 0, bm, blockIdx.x * 128);
}

__global__ void __launch_bounds__(256, 2) gemmU_kernel(
    const uint32_t* __restrict__ Ah, const uint32_t* __restrict__ Al,
    const uint32_t* __restrict__ Bh, const uint32_t* __restrict__ Bl,
    const float* __restrict__ bias, float* __restrict__ C)
{
    gemm_tile(Ah, Al, Bh, Bl, bias, C, nullptr, nullptr, nullptr, nullptr,
              BATCH * TLEN, 1, blockIdx.y * 128, blockIdx.x * 128);
}

// ---------------------------------------------------------------------------
// Tensor-core attention: all mma bf16x3 (k16, ldmatrix) on hi/lo planes.
// dpt/cpp computed IN-KERNEL from the staged K/KP planes (dptcpp fused away).
// Softmax uses contiguous per-thread columns (c = 4*tx + j).
// ---------------------------------------------------------------------------
#define QW 36    // word stride for plane rows
#define SP 196   // S matrix stride (floats)

// word offsets
#define OFF_QH 0
#define OFF_QL 2304
#define OFF_BH 4608
#define OFF_BL 11520
#define OFF_VTH 18432
#define OFF_VTL 20736
#define OFF_PH 23040
#define OFF_PL 25344
#define OFF_DP 27648
#define OFF_CP 27712
#define OFF_SC 27840
#define OFF_LS 27904
#define OFF_PA 27968
#define OFF_PB 28032
#define ATTN_SMEM_BYTES (28096 * 4)

__global__ void __launch_bounds__(256, 2) attn_kernel(
    const uint32_t* __restrict__ Qh, const uint32_t* __restrict__ Ql,
    const uint32_t* __restrict__ Kh, const uint32_t* __restrict__ Kl,
    const uint32_t* __restrict__ Vth, const uint32_t* __restrict__ Vtl,
    const uint32_t* __restrict__ KPh, const uint32_t* __restrict__ KPl,
    const float* __restrict__ parma, const float* __restrict__ parmb,
    uint32_t* __restrict__ Oh, uint32_t* __restrict__ Ol)
{
    extern __shared__ uint32_t smw[];
    uint32_t* Qhs = smw + OFF_QH;       // [64][QW]
    uint32_t* Qls = smw + OFF_QL;
    uint32_t* Bhs = smw + OFF_BH;       // [192][QW]
    uint32_t* Bls = smw + OFF_BL;
    float* Ssm  = (float*)(smw + OFF_BH);   // [64][SP] aliases B planes
    uint32_t* Vths = smw + OFF_VTH;     // [64 s][QW]
    uint32_t* Vtls = smw + OFF_VTL;
    __nv_bfloat16* PH = (__nv_bfloat16*)(smw + OFF_PH);  // [64][72]
    __nv_bfloat16* PL = (__nv_bfloat16*)(smw + OFF_PL);
    float* dpts = (float*)(smw + OFF_DP);
    float* cpps = (float*)(smw + OFF_CP);
    float* scale_sm = (float*)(smw + OFF_SC);
    float* lsum_sm  = (float*)(smw + OFF_LS);
    float* pas = (float*)(smw + OFF_PA);   // parma[h][0..63]
    float* pbs = (float*)(smw + OFF_PB);   // parmb[h][0..63]

    const int tid  = threadIdx.x;
    const int lane = tid & 31;
    const int wid  = tid >> 5;
    const int g = lane >> 2;
    const int t = lane & 3;
    const int rm = (wid & 1) * 32;      // scores m-base
    const int cn = (wid >> 1) * 48;     // scores n-base
    const int sm0 = (wid & 3) * 16;     // PV m-slice
    const int pn0 = (wid >> 2) * 32;    // PV n-slice
    const int tx = tid & 15, ty = tid >> 4;
    const uint32_t lzq = (((lane & 15) * QW) + ((lane >> 4) << 2)) * 4;
    const uint32_t smb = (uint32_t)__cvta_generic_to_shared(smw);

    const int b = blockIdx.z, h = blockIdx.y;
    const int it = (int)gridDim.x - 1 - (int)blockIdx.x;
    const int I0 = it * 64;
    const int hw = h * 32;

    // Stage Q planes once; stage parma/parmb for this head
    for (int idx = tid; idx < 512; idx += 256) {
        int r = idx >> 3, w = (idx & 7) * 4;
        size_t gq = (size_t)(b * TLEN + I0 + r) * 512 + hw + w;
        cpa16(&Qhs[r * QW + w], &Qh[gq], true);
        cpa16(&Qls[r * QW + w], &Ql[gq], true);
    }
    CP_COMMIT();
    if (tid < 64) pas[tid] = parma[h * SDIM + tid];
    else if (tid < 128) pbs[tid - 64] = parmb[h * SDIM + tid - 64];

    float m_r[4], l_r[4];
    #pragma unroll
    for (int i = 0; i < 4; i++) { m_r[i] = -INFINITY; l_r[i] = 0.f; }
    float o_acc[4][4];
    #pragma unroll
    for (int n = 0; n < 4; n++)
        #pragma unroll
        for (int q = 0; q < 4; q++) o_acc[n][q] = 0.f;

    for (int jt = 0; jt <= it; jt++) {
        const int J0 = jt * 64;
        const int pbase = I0 + J0;
        const int d = I0 - J0;

        __syncthreads();

        // ---- Stage K planes, KP planes, Vt planes ----
        for (int idx = tid; idx < 512; idx += 256) {
            int c = idx >> 3, w = (idx & 7) * 4;
            size_t gk = (size_t)(b * TLEN + J0 + c) * 512 + hw + w;
            cpa16(&Bhs[c * QW + w], &Kh[gk], true);
            cpa16(&Bls[c * QW + w], &Kl[gk], true);
        }
        for (int idx = tid; idx < 1024; idx += 256) {
            int pl = idx >> 3, w = (idx & 7) * 4;
            int p = pbase + pl;
            bool v = p < P2;
            size_t gp = (size_t)(v ? p : 0) * 512 + hw + w;
            cpa16(&Bhs[(64 + pl) * QW + w], &KPh[gp], v);
            cpa16(&Bls[(64 + pl) * QW + w], &KPl[gp], v);
        }
        for (int idx = tid; idx < 512; idx += 256) {
            int s = idx >> 3, w = (idx & 7) * 4;
            size_t gv = ((size_t)((b * HEADS + h) * 64 + s)) * 512
                      + (J0 >> 1) + w;
            cpa16(&Vths[s * QW + w], &Vth[gv], true);
            cpa16(&Vtls[s * QW + w], &Vtl[gv], true);
        }
        CP_COMMIT();
        CP_WAIT0();
        __syncthreads();

        // ---- In-kernel dpt: dpts[j] = parma . K[j]  (4 threads per row) ----
        {
            int j = tid >> 2, q = tid & 3;
            const uint4* hh4 = (const uint4*)&Bhs[j * QW + q * 8];
            const uint4* ll4 = (const uint4*)&Bls[j * QW + q * 8];
            const float4* pa4 = (const float4*)&pas[q * 16];
            float s = 0.f;
            #pragma unroll
            for (int w = 0; w < 2; w++) {
                uint4 hh = hh4[w], ll = ll4[w];
                float4 a0 = pa4[2 * w], a1 = pa4[2 * w + 1];
                float2 f;
                f = brecon2(hh.x, ll.x); s = fmaf(a0.x, f.x, fmaf(a0.y, f.y, s));
                f = brecon2(hh.y, ll.y); s = fmaf(a0.z, f.x, fmaf(a0.w, f.y, s));
                f = brecon2(hh.z, ll.z); s = fmaf(a1.x, f.x, fmaf(a1.y, f.y, s));
                f = brecon2(hh.w, ll.w); s = fmaf(a1.z, f.x, fmaf(a1.w, f.y, s));
            }
            s += __shfl_xor_sync(0xffffffffu, s, 1);
            s += __shfl_xor_sync(0xffffffffu, s, 2);
            if (q == 0) dpts[j] = s;
        }
        // ---- In-kernel cpp: cpps[p] = parmb . KP[p] (2 threads per row) ----
        {
            int p = tid >> 1, hf = tid & 1;
            const uint4* hh4 = (const uint4*)&Bhs[(64 + p) * QW + hf * 16];
            const uint4* ll4 = (const uint4*)&Bls[(64 + p) * QW + hf * 16];
            const float4* pb4 = (const float4*)&pbs[hf * 32];
            float s = 0.f;
            #pragma unroll
            for (int w = 0; w < 4; w++) {
                uint4 hh = hh4[w], ll = ll4[w];
                float4 a0 = pb4[2 * w], a1 = pb4[2 * w + 1];
                float2 f;
                f = brecon2(hh.x, ll.x); s = fmaf(a0.x, f.x, fmaf(a0.y, f.y, s));
                f = brecon2(hh.y, ll.y); s = fmaf(a0.z, f.x, fmaf(a0.w, f.y, s));
                f = brecon2(hh.z, ll.z); s = fmaf(a1.x, f.x, fmaf(a1.y, f.y, s));
                f = brecon2(hh.w, ll.w); s = fmaf(a1.z, f.x, fmaf(a1.w, f.y, s));
            }
            s += __shfl_xor_sync(0xffffffffu, s, 1);
            if (hf == 0) cpps[p] = s;
        }

        // Fragment need-masks (warp-uniform)
        bool need[2][6];
        #pragma unroll
        for (int mi = 0; mi < 2; mi++) {
            int m0 = rm + 16 * mi;
            int cmax = m0 + 15 + d; if (cmax > 63) cmax = 63;
            #pragma unroll
            for (int nt = 0; nt < 6; nt++) {
                int n0 = cn + nt * 8;
                if (n0 < 64) {
                    need[mi][nt] = (n0 <= m0 + 15 + d);
                } else {
                    int pl0 = n0 - 64;
                    need[mi][nt] = (pl0 + 7 >= m0) && (pl0 <= m0 + 15 + cmax);
                }
            }
        }

        // ---- Scores mma: bf16x3 m16n8k16 via ldmatrix ----
        float sacc[2][6][4];
        #pragma unroll
        for (int mi = 0; mi < 2; mi++)
            #pragma unroll
            for (int n = 0; n < 6; n++)
                #pragma unroll
                for (int q = 0; q < 4; q++) sacc[mi][n][q] = 0.f;

        const uint32_t qh0 = smb + OFF_QH * 4 + lzq;
        const uint32_t ql0 = smb + OFF_QL * 4 + lzq;
        const uint32_t bh0b = smb + OFF_BH * 4 + lzq;
        const uint32_t bl0b = smb + OFF_BL * 4 + lzq;

        #pragma unroll
        for (int kc = 0; kc < 4; kc++) {
            const uint32_t kbB = (uint32_t)(kc * 8) * 4;
            uint32_t ah[2][4], al[2][4], bh[3][4], bl[3][4];
            #pragma unroll
            for (int mi = 0; mi < 2; mi++) {
                uint32_t ro = (uint32_t)((rm + 16 * mi) * QW) * 4 + kbB;
                ldm_x4(ah[mi], qh0 + ro);
                ldm_x4(al[mi], ql0 + ro);
            }
            #pragma unroll
            for (int p = 0; p < 3; p++) {
                uint32_t ro = (uint32_t)((cn + p * 16) * QW) * 4 + kbB;
                ldm_x4(bh[p], bh0b + ro);
                ldm_x4(bl[p], bl0b + ro);
            }
            #pragma unroll
            for (int nt = 0; nt < 6; nt++) {
                if (!need[0][nt] && !need[1][nt]) continue;
                int p = nt >> 1, o = nt & 1;
                uint32_t b0 = bh[p][o], b1 = bh[p][o + 2];
                uint32_t c0 = bl[p][o], c1 = bl[p][o + 2];
                if (need[0][nt])
                    mma_bf16_x3(sacc[0][nt], ah[0], al[0], b0, b1, c0, c1);
                if (need[1][nt])
                    mma_bf16_x3(sacc[1][nt], ah[1], al[1], b0, b1, c0, c1);
            }
        }

        __syncthreads();   // done reading B planes; overwrite as Ssm
        #pragma unroll
        for (int mi = 0; mi < 2; mi++) {
            int r0 = rm + 16 * mi + g;
            #pragma unroll
            for (int nt = 0; nt < 6; nt++) {
                if (!need[mi][nt]) continue;
                int n0 = cn + nt * 8 + 2 * t;
                Ssm[r0 * SP + n0]           = sacc[mi][nt][0];
                Ssm[r0 * SP + n0 + 1]       = sacc[mi][nt][1];
                Ssm[(r0 + 8) * SP + n0]     = sacc[mi][nt][2];
                Ssm[(r0 + 8) * SP + n0 + 1] = sacc[mi][nt][3];
            }
        }
        __syncthreads();

        // ---- Softmax (fp32 SIMT), contiguous columns c = 4*tx + j ----
        const float4 dp4 = *(const float4*)&dpts[4 * tx];
        #pragma unroll
        for (int i = 0; i < 4; i++) {
            int r = ty + 16 * i;
            float4 sk = *(const float4*)&Ssm[r * SP + 4 * tx];
            const float* erow = &Ssm[r * SP + 64 + r + 4 * tx];
            const float* crow = &cpps[r + 4 * tx];
            float sc[4];
            sc[0] = sk.x + erow[0] + dp4.x + crow[0];
            sc[1] = sk.y + erow[1] + dp4.y + crow[1];
            sc[2] = sk.z + erow[2] + dp4.z + crow[2];
            sc[3] = sk.w + erow[3] + dp4.w + crow[3];
            float mx = -INFINITY;
            #pragma unroll
            for (int j = 0; j < 4; j++) {
                int c = 4 * tx + j;
                if (c > r + d) sc[j] = -1e30f;
                mx = fmaxf(mx, sc[j]);
            }
            #pragma unroll
            for (int off = 8; off >= 1; off >>= 1)
                mx = fmaxf(mx, __shfl_xor_sync(0xffffffffu, mx, off));
            float mnew = fmaxf(m_r[i], mx);
            float scale = __expf(m_r[i] - mnew);
            m_r[i] = mnew;
            float p0 = __expf(sc[0] - mnew);
            float p1 = __expf(sc[1] - mnew);
            float p2 = __expf(sc[2] - mnew);
            float p3 = __expf(sc[3] - mnew);
            float rs = (p0 + p1) + (p2 + p3);
            uint32_t h01, l01, h23, l23;
            bsplit2(p0, p1, h01, l01);
            bsplit2(p2, p3, h23, l23);
            *(uint2*)&PH[r * 72 + 4 * tx] = make_uint2(h01, h23);
            *(uint2*)&PL[r * 72 + 4 * tx] = make_uint2(l01, l23);
            #pragma unroll
            for (int off = 8; off >= 1; off >>= 1)
                rs += __shfl_xor_sync(0xffffffffu, rs, off);
            l_r[i] = l_r[i] * scale + rs;
            if (tx == 0) {
                scale_sm[r] = scale;
                lsum_sm[r]  = l_r[i];
            }
        }
        __syncthreads();

        // ---- PV mma: O = O*scale + P @ Vt^T (bf16x3, ldmatrix) ----
        const float sA = scale_sm[sm0 + g];
        const float sB = scale_sm[sm0 + g + 8];
        #pragma unroll
        for (int nt = 0; nt < 4; nt++) {
            o_acc[nt][0] *= sA; o_acc[nt][1] *= sA;
            o_acc[nt][2] *= sB; o_acc[nt][3] *= sB;
        }
        const uint32_t ph0 = smb + OFF_PH * 4 + lzq;
        const uint32_t pl0b = smb + OFF_PL * 4 + lzq;
        const uint32_t vh0 = smb + OFF_VTH * 4 + lzq;
        const uint32_t vl0 = smb + OFF_VTL * 4 + lzq;
        #pragma unroll
        for (int kc = 0; kc < 4; kc++) {
            const uint32_t kbB = (uint32_t)(kc * 8) * 4;
            uint32_t ah[4], al[4], bh[2][4], bl[2][4];
            {
                uint32_t ro = (uint32_t)(sm0 * QW) * 4 + kbB;
                ldm_x4(ah, ph0 + ro);
                ldm_x4(al, pl0b + ro);
            }
            #pragma unroll
            for (int p = 0; p < 2; p++) {
                uint32_t ro = (uint32_t)((pn0 + p * 16) * QW) * 4 + kbB;
                ldm_x4(bh[p], vh0 + ro);
                ldm_x4(bl[p], vl0 + ro);
            }
            #pragma unroll
            for (int nt = 0; nt < 4; nt++) {
                int p = nt >> 1, o = nt & 1;
                mma_bf16_x3(o_acc[nt], ah, al,
                            bh[p][o], bh[p][o + 2], bl[p][o], bl[p][o + 2]);
            }
        }
    }

    __syncthreads();
    const float invA = 1.f / lsum_sm[sm0 + g];
    const float invB = 1.f / lsum_sm[sm0 + g + 8];
    const size_t row0 = (size_t)(b * TLEN + I0 + sm0 + g) * EDIM;
    const size_t row1 = row0 + 8 * EDIM;
    #pragma unroll
    for (int nt = 0; nt < 4; nt++) {
        size_t col = (size_t)h * SDIM + pn0 + nt * 8 + 2 * t;   // even
        uint32_t hA, lA, hB, lB;
        bsplit2(o_acc[nt][0] * invA, o_acc[nt][1] * invA, hA, lA);
        bsplit2(o_acc[nt][2] * invB, o_acc[nt][3] * invB, hB, lB);
        Oh[(row0 + col) >> 1] = hA;
        Ol[(row0 + col) >> 1] = lA;
        Oh[(row1 + col) >> 1] = hB;
        Ol[(row1 + col) >> 1] = lB;
    }
}

// ---------------------------------------------------------------------------
// Launch
// ---------------------------------------------------------------------------
extern "C" void kernel_launch(void* const* d_in, const int* in_sizes, int n_in,
                              void* d_out, int out_size)
{
    const float* x     = (const float*)d_in[0];
    const float* Wq    = (const float*)d_in[1];
    const float* Wk    = (const float*)d_in[2];
    const float* Wkp   = (const float*)d_in[3];
    const float* Wv    = (const float*)d_in[4];
    const float* Wu    = (const float*)d_in[5];
    const float* bu    = (const float*)d_in[6];
    const float* parma = (const float*)d_in[7];
    const float* parmb = (const float*)d_in[8];
    const float* pos   = (const float*)d_in[9];
    float* out = (float*)d_out;

    void *Xh, *Xl, *Ph, *Pl, *Wh, *Wl, *Qh, *Ql, *Kh, *Kl, *KPh, *KPl;
    void *Vth, *Vtl, *ATTh, *ATTl;
    cudaGetSymbolAddress(&Xh,  g_Xh);
    cudaGetSymbolAddress(&Xl,  g_Xl);
    cudaGetSymbolAddress(&Ph,  g_Psrch);
    cudaGetSymbolAddress(&Pl,  g_Psrcl);
    cudaGetSymbolAddress(&Wh,  g_Wh);
    cudaGetSymbolAddress(&Wl,  g_Wl);
    cudaGetSymbolAddress(&Qh,  g_Qh);
    cudaGetSymbolAddress(&Ql,  g_Ql);
    cudaGetSymbolAddress(&Kh,  g_Kh);
    cudaGetSymbolAddress(&Kl,  g_Kl);
    cudaGetSymbolAddress(&KPh, g_KPh);
    cudaGetSymbolAddress(&KPl, g_KPl);
    cudaGetSymbolAddress(&Vth, g_Vth);
    cudaGetSymbolAddress(&Vtl, g_Vtl);
    cudaGetSymbolAddress(&ATTh, g_ATTh);
    cudaGetSymbolAddress(&ATTl, g_ATTl);

    // 1) transpose + split weights into bf16 planes
    transpose5_kernel<<<dim3(32, 32, 5), dim3(32, 8)>>>(
        Wq, Wk, Wv, Wkp, Wu, (__nv_bfloat16*)Wh, (__nv_bfloat16*)Wl);

    // 2) split x and pos into planes
    const int xpairs = BATCH * TLEN * EDIM / 2;
    const int ppairs = P2 * EDIM / 2;
    cvt_planes_kernel<<<(xpairs + 255) / 256, 256>>>(
        (const float2*)x, (uint32_t*)Xh, (uint32_t*)Xl, xpairs);
    cvt_planes_kernel<<<(ppairs + 255) / 256, 256>>>(
        (const float2*)pos, (uint32_t*)Ph, (uint32_t*)Pl, ppairs);

    // 3) fused projections (padded z-grid; 2-stage pipeline)
    cudaFuncSetAttribute(fused_gemm_kernel,
                         cudaFuncAttributeMaxDynamicSharedMemorySize,
                         GEMM_SMEM_BYTES);
    fused_gemm_kernel<<<dim3(8, 32, 4), 256, GEMM_SMEM_BYTES>>>(
        (const uint32_t*)Xh, (const uint32_t*)Xl,
        (const uint32_t*)Ph, (const uint32_t*)Pl,
        (const uint32_t*)Wh, (const uint32_t*)Wl,
        (uint32_t*)Qh, (uint32_t*)Ql, (uint32_t*)Kh, (uint32_t*)Kl,
        (__nv_bfloat16*)Vth, (__nv_bfloat16*)Vtl,
        (uint32_t*)KPh, (uint32_t*)KPl);

    // 4) attention (all-bf16x3; dpt/cpp computed in-kernel; writes ATT planes)
    cudaFuncSetAttribute(attn_kernel,
                         cudaFuncAttributeMaxDynamicSharedMemorySize,
                         ATTN_SMEM_BYTES);
    attn_kernel<<<dim3(TLEN / 64, HEADS, BATCH), 256, ATTN_SMEM_BYTES>>>(
        (const uint32_t*)Qh, (const uint32_t*)Ql,
        (const uint32_t*)Kh, (const uint32_t*)Kl,
        (const uint32_t*)Vth, (const uint32_t*)Vtl,
        (const uint32_t*)KPh, (const uint32_t*)KPl,
        parma, parmb, (uint32_t*)ATTh, (uint32_t*)ATTl);

    // 5) output projection (+bias, bf16x3)
    cudaFuncSetAttribute(gemmU_kernel,
                         cudaFuncAttributeMaxDynamicSharedMemorySize,
                         GEMM_SMEM_BYTES);
    gemmU_kernel<<<dim3(8, 32), 256, GEMM_SMEM_BYTES>>>(
        (const uint32_t*)ATTh, (const uint32_t*)ATTl,
        (const uint32_t*)Wh + 4 * (size_t)EDIM * EDIM / 2,
        (const uint32_t*)Wl + 4 * (size_t)EDIM * EDIM / 2,
        bu, out);
}